// round 11
// baseline (speedup 1.0000x reference)
#include <cuda_runtime.h>
#include <math.h>

#define NODES 8672
#define ND    2528
#define HIDD  128
#define BSZ   32
#define LL1   79
#define LL2   192
#define E1T   5120
#define E2T   12800
#define ETOT  17920
#define SEIN  15168
#define SEHID 2000
#define SEK   271      // 79 + 192

// ---------------- device scratch ----------------
__device__ float g_x   [NODES*HIDD];
__device__ float g_h   [NODES*HIDD];
__device__ float g_o   [NODES*HIDD];     // unnormalized numerator
__device__ float g_xsum[NODES*HIDD];
__device__ float g_hs[NODES], g_hd[NODES], g_den[NODES];
__device__ float g_rs[NODES];            // row sums / 256
__device__ float g_sew[SEK*SEHID];       // [0:79) WL rows, [79:271) WP rows
__device__ float g_c1[BSZ*SEHID];
__device__ float g_c2[BSZ*SEIN];
__device__ float g_wl[BSZ*LL1], g_wp[BSZ*LL2];
__device__ float g_xx[BSZ*256];

__device__ __forceinline__ float lrelu(float x) { return x > 0.f ? x : 0.2f * x; }

// ---- f32x2 helpers ----
__device__ __forceinline__ void fma2(unsigned long long& d, unsigned long long a, unsigned long long b) {
    asm("fma.rn.f32x2 %0, %1, %2, %0;" : "+l"(d) : "l"(a), "l"(b));
}
__device__ __forceinline__ unsigned long long pack2(float x, float y) {
    unsigned long long r;
    asm("mov.b64 %0, {%1, %2};" : "=l"(r) : "f"(x), "f"(y));
    return r;
}
__device__ __forceinline__ void unpack2(unsigned long long v, float& x, float& y) {
    asm("mov.b64 {%0, %1}, %2;" : "=f"(x), "=f"(y) : "l"(v));
}
__device__ __forceinline__ void lds_v2u64(unsigned saddr, unsigned long long& a, unsigned long long& b) {
    asm volatile("ld.shared.v2.u64 {%0,%1}, [%2];" : "=l"(a), "=l"(b) : "r"(saddr));
}

// ---------------- combined zero-init ----------------
__global__ void k_init() {
    int idx = blockIdx.x * blockDim.x + threadIdx.x;
    if (idx < SEK * SEHID) g_sew[idx] = 0.f;
    if (idx < BSZ * SEHID) g_c1[idx] = 0.f;
    if (idx < BSZ * SEIN)  g_c2[idx] = 0.f;
    if (idx < BSZ * 256)   g_xx[idx] = 0.f;
}

// ---------------- fused embedding MLP (8 rows / block) ----------------
__global__ void k_embed(const float* __restrict__ x1, const float* __restrict__ x2,
                        const float* __restrict__ w1, const float* __restrict__ b1,
                        const float* __restrict__ w2, const float* __restrict__ b2) {
    __shared__ float xsT[52][8];
    __shared__ float hbT[128][8];
    int tid = threadIdx.x;
    int r0 = blockIdx.x * 8;
    for (int idx = tid; idx < 8 * 52; idx += 128) {
        int r = idx / 52, c = idx - r * 52;
        int row = r0 + r;
        xsT[c][r] = (row < ND) ? x1[row * 52 + c] : x2[(row - ND) * 52 + c];
    }
    __syncthreads();
    float acc[8] = {0.f,0.f,0.f,0.f,0.f,0.f,0.f,0.f};
    for (int k = 0; k < 52; k++) {
        float w = w1[k * 128 + tid];
        float4 a0 = *(const float4*)&xsT[k][0];
        float4 a1 = *(const float4*)&xsT[k][4];
        acc[0] = fmaf(a0.x, w, acc[0]); acc[1] = fmaf(a0.y, w, acc[1]);
        acc[2] = fmaf(a0.z, w, acc[2]); acc[3] = fmaf(a0.w, w, acc[3]);
        acc[4] = fmaf(a1.x, w, acc[4]); acc[5] = fmaf(a1.y, w, acc[5]);
        acc[6] = fmaf(a1.z, w, acc[6]); acc[7] = fmaf(a1.w, w, acc[7]);
    }
    float bv = b1[tid];
#pragma unroll
    for (int r = 0; r < 8; r++) hbT[tid][r] = fmaxf(acc[r] + bv, 0.f);
    __syncthreads();
    float a2[8] = {0.f,0.f,0.f,0.f,0.f,0.f,0.f,0.f};
    for (int k = 0; k < 128; k++) {
        float w = w2[k * 128 + tid];
        float4 a0 = *(const float4*)&hbT[k][0];
        float4 a1 = *(const float4*)&hbT[k][4];
        a2[0] = fmaf(a0.x, w, a2[0]); a2[1] = fmaf(a0.y, w, a2[1]);
        a2[2] = fmaf(a0.z, w, a2[2]); a2[3] = fmaf(a0.w, w, a2[3]);
        a2[4] = fmaf(a1.x, w, a2[4]); a2[5] = fmaf(a1.y, w, a2[5]);
        a2[6] = fmaf(a1.z, w, a2[6]); a2[7] = fmaf(a1.w, w, a2[7]);
    }
    float b2v = b2[tid];
#pragma unroll
    for (int r = 0; r < 8; r++)
        g_x[(r0 + r) * 128 + tid] = fmaxf(a2[r] + b2v, 0.f);
}

// ---------------- GAT: h = x@W, attn dots, self-loop init ----------------
__global__ void k_gat_h(const float* __restrict__ gat_w, const float* __restrict__ gat_as,
                        const float* __restrict__ gat_ad, int layer) {
    __shared__ float xsT[128][8];
    __shared__ float redS[8][4], redD[8][4];
    __shared__ float sws[8];
    int tid = threadIdx.x;
    int r0 = blockIdx.x * 8;
    for (int idx = tid; idx < 1024; idx += 128) {
        int r = idx >> 7, k = idx & 127;
        xsT[k][r] = g_x[(r0 + r) * 128 + k];
    }
    __syncthreads();
    int widx = (r0 < ND ? 0 : 3) + layer;
    const float* W = gat_w + (size_t)widx * 16384;
    float acc[8] = {0.f,0.f,0.f,0.f,0.f,0.f,0.f,0.f};
    for (int k = 0; k < 128; k++) {
        float w = W[k * 128 + tid];
        float4 a0 = *(const float4*)&xsT[k][0];
        float4 a1 = *(const float4*)&xsT[k][4];
        acc[0] = fmaf(a0.x, w, acc[0]); acc[1] = fmaf(a0.y, w, acc[1]);
        acc[2] = fmaf(a0.z, w, acc[2]); acc[3] = fmaf(a0.w, w, acc[3]);
        acc[4] = fmaf(a1.x, w, acc[4]); acc[5] = fmaf(a1.y, w, acc[5]);
        acc[6] = fmaf(a1.z, w, acc[6]); acc[7] = fmaf(a1.w, w, acc[7]);
    }
    float asv = gat_as[widx * 128 + tid], adv = gat_ad[widx * 128 + tid];
    int lane = tid & 31, wrp = tid >> 5;
#pragma unroll
    for (int r = 0; r < 8; r++) {
        float ps = acc[r] * asv, pd = acc[r] * adv;
#pragma unroll
        for (int o = 16; o > 0; o >>= 1) {
            ps += __shfl_down_sync(0xffffffffu, ps, o);
            pd += __shfl_down_sync(0xffffffffu, pd, o);
        }
        if (lane == 0) { redS[r][wrp] = ps; redD[r][wrp] = pd; }
    }
    __syncthreads();
    if (tid < 8) {
        float hs = redS[tid][0] + redS[tid][1] + redS[tid][2] + redS[tid][3];
        float hd = redD[tid][0] + redD[tid][1] + redD[tid][2] + redD[tid][3];
        g_hs[r0 + tid] = hs; g_hd[r0 + tid] = hd;
        float w = expf(lrelu(hs + hd));   // self-loop weight (shift-free softmax)
        g_den[r0 + tid] = w;
        sws[tid] = w;
    }
    __syncthreads();
#pragma unroll
    for (int r = 0; r < 8; r++) {
        g_h[(r0 + r) * 128 + tid] = acc[r];
        g_o[(r0 + r) * 128 + tid] = sws[r] * acc[r];
    }
}

// per-edge: accumulate unnormalized numerator + denominator in ONE pass
__global__ void k_edge(const int* __restrict__ dei, const int* __restrict__ pei) {
    int gid = blockIdx.x * blockDim.x + threadIdx.x;
    int e = gid >> 5, lane = gid & 31;
    if (e >= ETOT) return;
    int s, d;
    if (e < E1T) { s = dei[e]; d = dei[E1T + e]; }
    else { int q = e - E1T; s = pei[q] + ND; d = pei[E2T + q] + ND; }
    float w = 0.f;
    if (lane == 0) {
        w = expf(lrelu(g_hs[s] + g_hd[d]));
        atomicAdd(&g_den[d], w);
    }
    w = __shfl_sync(0xffffffffu, w, 0);
#pragma unroll
    for (int c = 0; c < 4; c++) {
        int f = lane + 32 * c;
        atomicAdd(&g_o[d * 128 + f], w * g_h[s * 128 + f]);
    }
}

// normalize + bias + relu + residual accum; last layer also does row sums
__global__ void k_final(const float* __restrict__ gat_b, int layer) {
    int gid = blockIdx.x * blockDim.x + threadIdx.x;
    int n = gid >> 5, lane = gid & 31;
    if (n >= NODES) return;
    int widx = (n < ND ? 0 : 3) + layer;
    float inv = 1.0f / g_den[n];
    float4 o = ((const float4*)&g_o[n * 128])[lane];
    float4 b = ((const float4*)&gat_b[widx * 128])[lane];
    float4 v;
    v.x = fmaxf(fmaf(o.x, inv, b.x), 0.f);
    v.y = fmaxf(fmaf(o.y, inv, b.y), 0.f);
    v.z = fmaxf(fmaf(o.z, inv, b.z), 0.f);
    v.w = fmaxf(fmaf(o.w, inv, b.w), 0.f);
    float4* xs4 = (float4*)&g_xsum[n * 128];
    float4 sum;
    if (layer == 0) sum = v;
    else {
        float4 p = xs4[lane];
        sum.x = p.x + v.x; sum.y = p.y + v.y; sum.z = p.z + v.z; sum.w = p.w + v.w;
    }
    xs4[lane] = sum;
    if (layer < 2) ((float4*)&g_x[n * 128])[lane] = v;
    else {
        float s = sum.x + sum.y + sum.z + sum.w;
#pragma unroll
        for (int o2 = 16; o2 > 0; o2 >>= 1) s += __shfl_down_sync(0xffffffffu, s, o2);
        if (lane == 0) g_rs[n] = s * (1.f / 256.f);
    }
}

// ---------------- fused SE weight reduction: read se1_w ONCE ----------------
// grid (16 ncol, 8 jgroup, 4 igroup); block 128.
// WL[i,n] += local sum over 24 j ; WP[j,n] += local sum over ~20 i
__global__ void k_wred(const float* __restrict__ W1) {
    int n = blockIdx.x * 128 + threadIdx.x;
    if (n >= SEHID) return;
    int j0 = blockIdx.y * 24;
    int i0 = blockIdx.z * 20;
    int i1 = min(LL1, i0 + 20);
    float wp[24];
#pragma unroll
    for (int jj = 0; jj < 24; jj++) wp[jj] = 0.f;
    for (int i = i0; i < i1; i++) {
        const float* p = W1 + (size_t)(i * 192 + j0) * SEHID + n;
        float wl = 0.f;
#pragma unroll
        for (int jj = 0; jj < 24; jj++) {
            float v = p[(size_t)jj * SEHID];
            wp[jj] += v;
            wl += v;
        }
        atomicAdd(&g_sew[i * SEHID + n], wl);
    }
#pragma unroll
    for (int jj = 0; jj < 24; jj++)
        atomicAdd(&g_sew[(LL1 + j0 + jj) * SEHID + n], wp[jj]);
}

// c1(32,2000) += [rl|rp](32,271-chunk) @ g_sew ; split-K=8, bias on y==0
__global__ void k_se1(const float* __restrict__ bias) {
    __shared__ float AsT[35][36];
    int tid = threadIdx.x;
    int n = blockIdx.x * 128 + tid;
    int k0 = blockIdx.y * 34;
    int k1 = min(SEK, k0 + 34);
    int klen = k1 - k0;
    for (int idx = tid; idx < 32 * klen; idx += 128) {
        int m = idx / klen, kk = idx - m * klen;
        int k = k0 + kk;
        float v = (k < LL1) ? g_rs[m * LL1 + k] : g_rs[ND + m * LL2 + (k - LL1)];
        AsT[kk][m] = v;
    }
    __syncthreads();
    if (n >= SEHID) return;
    unsigned long long acc[16];
    if (blockIdx.y == 0) {
        float bn = bias[n];
        unsigned long long bp = pack2(bn, bn);
#pragma unroll
        for (int q = 0; q < 16; q++) acc[q] = bp;
    } else {
#pragma unroll
        for (int q = 0; q < 16; q++) acc[q] = 0ULL;
    }
    unsigned sbase = (unsigned)__cvta_generic_to_shared(&AsT[0][0]);
#pragma unroll 2
    for (int kk = 0; kk < klen; kk++) {
        float w = g_sew[(k0 + kk) * SEHID + n];
        unsigned long long w2 = pack2(w, w);
        unsigned row = sbase + (unsigned)kk * 144;
#pragma unroll
        for (int q = 0; q < 8; q++) {
            unsigned long long a0, a1;
            lds_v2u64(row + q * 16, a0, a1);
            fma2(acc[2 * q], a0, w2);
            fma2(acc[2 * q + 1], a1, w2);
        }
    }
#pragma unroll
    for (int q = 0; q < 16; q++) {
        float lo, hi; unpack2(acc[q], lo, hi);
        atomicAdd(&g_c1[(2 * q) * SEHID + n], lo);
        atomicAdd(&g_c1[(2 * q + 1) * SEHID + n], hi);
    }
}

// c2 += relu(c1) @ se2_w + bias ; f32x2, split-K=8 (chunks of 250)
#define TK2 50
__global__ void k_se2(const float* __restrict__ W, const float* __restrict__ bias) {
    __shared__ float AsT[TK2][36];
    int tid = threadIdx.x;
    int n = blockIdx.x * 128 + tid;
    int k0 = blockIdx.y * 250;
    bool valid = (n < SEIN);
    unsigned long long acc[16];
    if (blockIdx.y == 0 && valid) {
        float bn = bias[n];
        unsigned long long bp = pack2(bn, bn);
#pragma unroll
        for (int q = 0; q < 16; q++) acc[q] = bp;
    } else {
#pragma unroll
        for (int q = 0; q < 16; q++) acc[q] = 0ULL;
    }
    unsigned sbase = (unsigned)__cvta_generic_to_shared(&AsT[0][0]);
    for (int kk = k0; kk < k0 + 250; kk += TK2) {
        __syncthreads();
        for (int idx = tid; idx < 32 * TK2; idx += 128) {
            int m = idx / TK2, t = idx - m * TK2;
            AsT[t][m] = fmaxf(g_c1[m * SEHID + kk + t], 0.f);
        }
        __syncthreads();
        if (valid) {
            const float* wp = W + (size_t)kk * SEIN + n;
#pragma unroll 5
            for (int t = 0; t < TK2; t++) {
                float w = wp[(size_t)t * SEIN];
                unsigned long long w2 = pack2(w, w);
                unsigned row = sbase + (unsigned)t * 144;
#pragma unroll
                for (int q = 0; q < 8; q++) {
                    unsigned long long a0, a1;
                    lds_v2u64(row + q * 16, a0, a1);
                    fma2(acc[2 * q], a0, w2);
                    fma2(acc[2 * q + 1], a1, w2);
                }
            }
        }
    }
    if (valid) {
#pragma unroll
        for (int q = 0; q < 16; q++) {
            float lo, hi; unpack2(acc[q], lo, hi);
            atomicAdd(&g_c2[(size_t)(2 * q) * SEIN + n], lo);
            atomicAdd(&g_c2[(size_t)(2 * q + 1) * SEIN + n], hi);
        }
    }
}

// sigmoid folded; wl[b,i] and wp[b,j] weighted sums
__global__ void k_wlp(const float* __restrict__ inter) {
    int gid = blockIdx.x * blockDim.x + threadIdx.x;
    int w = gid >> 5, lane = gid & 31;
    if (w < BSZ * LL1) {
        int b = w / LL1, i = w - b * LL1;
        float s = 0.f;
        for (int j = lane; j < LL2; j += 32) {
            int idx = b * SEIN + i * LL2 + j;
            float sg = 1.f / (1.f + expf(-g_c2[idx]));
            s += sg / inter[idx];
        }
#pragma unroll
        for (int o = 16; o > 0; o >>= 1) s += __shfl_down_sync(0xffffffffu, s, o);
        if (lane == 0) g_wl[w] = s * (1.f / (float)SEIN);
    } else if (w < BSZ * (LL1 + LL2)) {
        int w2i = w - BSZ * LL1;
        int b = w2i / LL2, j = w2i - b * LL2;
        float s = 0.f;
        for (int i = lane; i < LL1; i += 32) {
            int idx = b * SEIN + i * LL2 + j;
            float sg = 1.f / (1.f + expf(-g_c2[idx]));
            s += sg / inter[idx];
        }
#pragma unroll
        for (int o = 16; o > 0; o >>= 1) s += __shfl_down_sync(0xffffffffu, s, o);
        if (lane == 0) g_wp[w2i] = s * (1.f / (float)SEIN);
    }
}

// xx[b, :] weighted sums, split over 8 segments + atomicAdd (g_xx zero-inited)
__global__ void k_fuse() {
    int b = blockIdx.x, seg = blockIdx.y, t = threadIdx.x;   // 128 threads
    float acc = 0.f;
    if (seg < 4) {
        int i0 = seg * 20, i1 = min(LL1, i0 + 20);
        for (int i = i0; i < i1; i++)
            acc = fmaf(g_wl[b * LL1 + i], g_xsum[(b * LL1 + i) * HIDD + t], acc);
        atomicAdd(&g_xx[b * 256 + t], acc);
    } else {
        int j0 = (seg - 4) * 48, j1 = j0 + 48;
        for (int j = j0; j < j1; j++)
            acc = fmaf(g_wp[b * LL2 + j], g_xsum[(ND + b * LL2 + j) * HIDD + t], acc);
        atomicAdd(&g_xx[b * 256 + 128 + t], acc);
    }
}

// ---------------- fused head MLP: 128 threads, float4 weights ----------------
__global__ void __launch_bounds__(128) k_head(
    const float* __restrict__ fc1_w, const float* __restrict__ fc1_b,
    const float* __restrict__ fc2_w, const float* __restrict__ fc2_b,
    const float* __restrict__ fc3_w, const float* __restrict__ fc3_b,
    const float* __restrict__ fc4_w, const float* __restrict__ fc4_b,
    const float* __restrict__ out_w, const float* __restrict__ out_b,
    float* __restrict__ dout) {
    int b = blockIdx.x, t = threadIdx.x;
    __shared__ float s0[256], s1[512], s2[256], s3[128], s4[64];
    s0[t] = g_xx[b * 256 + t];
    s0[t + 128] = g_xx[b * 256 + 128 + t];
    __syncthreads();
    // fc1: 256 -> 512, 4 outs/thread (h1 pre-relu is an output)
    {
        float4 acc = *(const float4*)&fc1_b[4 * t];
        for (int k = 0; k < 256; k++) {
            float a = s0[k];
            float4 w = *(const float4*)&fc1_w[k * 512 + 4 * t];
            acc.x = fmaf(a, w.x, acc.x); acc.y = fmaf(a, w.y, acc.y);
            acc.z = fmaf(a, w.z, acc.z); acc.w = fmaf(a, w.w, acc.w);
        }
        *(float4*)&dout[32 + b * 512 + 4 * t] = acc;
        s1[4*t]   = fmaxf(acc.x, 0.f); s1[4*t+1] = fmaxf(acc.y, 0.f);
        s1[4*t+2] = fmaxf(acc.z, 0.f); s1[4*t+3] = fmaxf(acc.w, 0.f);
    }
    __syncthreads();
    // fc2: 512 -> 256
    if (t < 64) {
        float4 acc = *(const float4*)&fc2_b[4 * t];
        for (int k = 0; k < 512; k++) {
            float a = s1[k];
            float4 w = *(const float4*)&fc2_w[k * 256 + 4 * t];
            acc.x = fmaf(a, w.x, acc.x); acc.y = fmaf(a, w.y, acc.y);
            acc.z = fmaf(a, w.z, acc.z); acc.w = fmaf(a, w.w, acc.w);
        }
        s2[4*t]   = fmaxf(acc.x, 0.f); s2[4*t+1] = fmaxf(acc.y, 0.f);
        s2[4*t+2] = fmaxf(acc.z, 0.f); s2[4*t+3] = fmaxf(acc.w, 0.f);
    }
    __syncthreads();
    // fc3: 256 -> 128
    if (t < 32) {
        float4 acc = *(const float4*)&fc3_b[4 * t];
        for (int k = 0; k < 256; k++) {
            float a = s2[k];
            float4 w = *(const float4*)&fc3_w[k * 128 + 4 * t];
            acc.x = fmaf(a, w.x, acc.x); acc.y = fmaf(a, w.y, acc.y);
            acc.z = fmaf(a, w.z, acc.z); acc.w = fmaf(a, w.w, acc.w);
        }
        s3[4*t]   = fmaxf(acc.x, 0.f); s3[4*t+1] = fmaxf(acc.y, 0.f);
        s3[4*t+2] = fmaxf(acc.z, 0.f); s3[4*t+3] = fmaxf(acc.w, 0.f);
    }
    __syncthreads();
    // fc4: 128 -> 64
    if (t < 16) {
        float4 acc = *(const float4*)&fc4_b[4 * t];
        for (int k = 0; k < 128; k++) {
            float a = s3[k];
            float4 w = *(const float4*)&fc4_w[k * 64 + 4 * t];
            acc.x = fmaf(a, w.x, acc.x); acc.y = fmaf(a, w.y, acc.y);
            acc.z = fmaf(a, w.z, acc.z); acc.w = fmaf(a, w.w, acc.w);
        }
        s4[4*t]   = fmaxf(acc.x, 0.f); s4[4*t+1] = fmaxf(acc.y, 0.f);
        s4[4*t+2] = fmaxf(acc.z, 0.f); s4[4*t+3] = fmaxf(acc.w, 0.f);
    }
    __syncthreads();
    // out: 64 -> 1
    if (t < 32) {
        float acc = s4[t] * out_w[t] + s4[t + 32] * out_w[t + 32];
#pragma unroll
        for (int o = 16; o > 0; o >>= 1) acc += __shfl_down_sync(0xffffffffu, acc, o);
        if (t == 0) dout[b] = acc + out_b[0];
    }
}

extern "C" void kernel_launch(void* const* d_in, const int* in_sizes, int n_in,
                              void* d_out, int out_size) {
    const float* x1    = (const float*)d_in[0];
    const float* x2    = (const float*)d_in[1];
    const float* inter = (const float*)d_in[2];
    const int*   dei   = (const int*)d_in[3];
    const int*   pei   = (const int*)d_in[4];
    const float* w1    = (const float*)d_in[5];
    const float* b1    = (const float*)d_in[6];
    const float* w2    = (const float*)d_in[7];
    const float* b2    = (const float*)d_in[8];
    const float* gat_w = (const float*)d_in[9];
    const float* gat_as= (const float*)d_in[10];
    const float* gat_ad= (const float*)d_in[11];
    const float* gat_b = (const float*)d_in[12];
    const float* se1_w = (const float*)d_in[13];
    const float* se1_b = (const float*)d_in[14];
    const float* se2_w = (const float*)d_in[15];
    const float* se2_b = (const float*)d_in[16];
    const float* fc1_w = (const float*)d_in[17];
    const float* fc1_b = (const float*)d_in[18];
    const float* fc2_w = (const float*)d_in[19];
    const float* fc2_b = (const float*)d_in[20];
    const float* fc3_w = (const float*)d_in[21];
    const float* fc3_b = (const float*)d_in[22];
    const float* fc4_w = (const float*)d_in[23];
    const float* fc4_b = (const float*)d_in[24];
    const float* out_w = (const float*)d_in[25];
    const float* out_b = (const float*)d_in[26];
    float* dout = (float*)d_out;

    k_init<<<(SEK * SEHID + 255) / 256, 256>>>();
    k_wred<<<dim3(16, 8, 4), 128>>>(se1_w);

    k_embed<<<NODES / 8, 128>>>(x1, x2, w1, b1, w2, b2);

    for (int l = 0; l < 3; l++) {
        k_gat_h<<<NODES / 8, 128>>>(gat_w, gat_as, gat_ad, l);
        k_edge<<<(ETOT * 32 + 255) / 256, 256>>>(dei, pei);
        k_final<<<(NODES * 32 + 255) / 256, 256>>>(gat_b, l);
    }

    k_se1<<<dim3(16, 8), 128>>>(se1_b);
    k_se2<<<dim3(119, 8), 128>>>(se2_w, se2_b);

    k_wlp<<<(BSZ * (LL1 + LL2) * 32 + 255) / 256, 256>>>(inter);
    k_fuse<<<dim3(BSZ, 8), 128>>>();

    k_head<<<BSZ, 128>>>(fc1_w, fc1_b, fc2_w, fc2_b, fc3_w, fc3_b,
                         fc4_w, fc4_b, out_w, out_b, dout);
}

// round 12
// speedup vs baseline: 1.4570x; 1.4570x over previous
#include <cuda_runtime.h>
#include <math.h>

#define NODES 8672
#define ND    2528
#define HIDD  128
#define BSZ   32
#define LL1   79
#define LL2   192
#define E1T   5120
#define E2T   12800
#define ETOT  17920
#define SEIN  15168
#define SEHID 2000
#define SEK   271      // 79 + 192

// ---------------- device scratch ----------------
__device__ float g_x   [NODES*HIDD];
__device__ float g_h   [NODES*HIDD];
__device__ float g_o   [NODES*HIDD];     // unnormalized numerator
__device__ float g_xsum[NODES*HIDD];
__device__ float g_hs[NODES], g_hd[NODES], g_den[NODES];
__device__ float g_rs[NODES];            // row sums / 256
__device__ float g_sew[SEK*SEHID];       // [0:79) WL rows, [79:271) WP rows
__device__ float g_c1[BSZ*SEHID];
__device__ float g_c2[BSZ*SEIN];
__device__ float g_wl[BSZ*LL1], g_wp[BSZ*LL2];
__device__ float g_xx[BSZ*256];

__device__ __forceinline__ float lrelu(float x) { return x > 0.f ? x : 0.2f * x; }

// ---- f32x2 helpers ----
__device__ __forceinline__ void fma2(unsigned long long& d, unsigned long long a, unsigned long long b) {
    asm("fma.rn.f32x2 %0, %1, %2, %0;" : "+l"(d) : "l"(a), "l"(b));
}
__device__ __forceinline__ unsigned long long pack2(float x, float y) {
    unsigned long long r;
    asm("mov.b64 %0, {%1, %2};" : "=l"(r) : "f"(x), "f"(y));
    return r;
}
__device__ __forceinline__ void unpack2(unsigned long long v, float& x, float& y) {
    asm("mov.b64 {%0, %1}, %2;" : "=f"(x), "=f"(y) : "l"(v));
}
__device__ __forceinline__ void lds_v2u64(unsigned saddr, unsigned long long& a, unsigned long long& b) {
    asm volatile("ld.shared.v2.u64 {%0,%1}, [%2];" : "=l"(a), "=l"(b) : "r"(saddr));
}

// ---------------- fused embedding MLP (8 rows / block) ----------------
__global__ void k_embed(const float* __restrict__ x1, const float* __restrict__ x2,
                        const float* __restrict__ w1, const float* __restrict__ b1,
                        const float* __restrict__ w2, const float* __restrict__ b2) {
    __shared__ float xsT[52][8];
    __shared__ float hbT[128][8];
    int tid = threadIdx.x;
    int r0 = blockIdx.x * 8;
    for (int idx = tid; idx < 8 * 52; idx += 128) {
        int r = idx / 52, c = idx - r * 52;
        int row = r0 + r;
        xsT[c][r] = (row < ND) ? x1[row * 52 + c] : x2[(row - ND) * 52 + c];
    }
    __syncthreads();
    float acc[8] = {0.f,0.f,0.f,0.f,0.f,0.f,0.f,0.f};
    for (int k = 0; k < 52; k++) {
        float w = w1[k * 128 + tid];
        float4 a0 = *(const float4*)&xsT[k][0];
        float4 a1 = *(const float4*)&xsT[k][4];
        acc[0] = fmaf(a0.x, w, acc[0]); acc[1] = fmaf(a0.y, w, acc[1]);
        acc[2] = fmaf(a0.z, w, acc[2]); acc[3] = fmaf(a0.w, w, acc[3]);
        acc[4] = fmaf(a1.x, w, acc[4]); acc[5] = fmaf(a1.y, w, acc[5]);
        acc[6] = fmaf(a1.z, w, acc[6]); acc[7] = fmaf(a1.w, w, acc[7]);
    }
    float bv = b1[tid];
#pragma unroll
    for (int r = 0; r < 8; r++) hbT[tid][r] = fmaxf(acc[r] + bv, 0.f);
    __syncthreads();
    float a2[8] = {0.f,0.f,0.f,0.f,0.f,0.f,0.f,0.f};
    for (int k = 0; k < 128; k++) {
        float w = w2[k * 128 + tid];
        float4 a0 = *(const float4*)&hbT[k][0];
        float4 a1 = *(const float4*)&hbT[k][4];
        a2[0] = fmaf(a0.x, w, a2[0]); a2[1] = fmaf(a0.y, w, a2[1]);
        a2[2] = fmaf(a0.z, w, a2[2]); a2[3] = fmaf(a0.w, w, a2[3]);
        a2[4] = fmaf(a1.x, w, a2[4]); a2[5] = fmaf(a1.y, w, a2[5]);
        a2[6] = fmaf(a1.z, w, a2[6]); a2[7] = fmaf(a1.w, w, a2[7]);
    }
    float b2v = b2[tid];
#pragma unroll
    for (int r = 0; r < 8; r++)
        g_x[(r0 + r) * 128 + tid] = fmaxf(a2[r] + b2v, 0.f);
}

// ---------------- GAT GEMM: 16 rows x 128 cols / block, 4x4 tile / thread ----
// warp w owns rows 4w..4w+3 (entire 128 cols) -> per-row attn dots reduce
// within a single warp.
__global__ void __launch_bounds__(128) k_gat_h(
        const float* __restrict__ gat_w, const float* __restrict__ gat_as,
        const float* __restrict__ gat_ad, int layer) {
    __shared__ float xsT[128][16];     // [k][r]
    __shared__ float sws[16];
    int tid = threadIdx.x;
    int r0 = blockIdx.x * 16;          // ND=2528 divisible by 16: no straddle
    // load 16 rows of g_x transposed (coalesced on k)
#pragma unroll
    for (int r = tid >> 7, it = 0; it < 16; it++) {   // dummy to keep style
        break;
    }
    for (int idx = tid; idx < 16 * 128; idx += 128) {
        int r = idx >> 7, k = idx & 127;
        xsT[k][r] = g_x[(r0 + r) * 128 + k];
    }
    __syncthreads();
    int widx = (r0 < ND ? 0 : 3) + layer;
    const float* W = gat_w + (size_t)widx * 16384;
    int col = (tid & 31) * 4;
    int rq = tid >> 5;                 // warp id = row-quad id
    float acc[4][4];
#pragma unroll
    for (int r = 0; r < 4; r++)
#pragma unroll
        for (int c = 0; c < 4; c++) acc[r][c] = 0.f;
    for (int k = 0; k < 128; k++) {
        float4 w = *(const float4*)&W[k * 128 + col];
        float4 a = *(const float4*)&xsT[k][rq * 4];
        acc[0][0] = fmaf(a.x, w.x, acc[0][0]); acc[0][1] = fmaf(a.x, w.y, acc[0][1]);
        acc[0][2] = fmaf(a.x, w.z, acc[0][2]); acc[0][3] = fmaf(a.x, w.w, acc[0][3]);
        acc[1][0] = fmaf(a.y, w.x, acc[1][0]); acc[1][1] = fmaf(a.y, w.y, acc[1][1]);
        acc[1][2] = fmaf(a.y, w.z, acc[1][2]); acc[1][3] = fmaf(a.y, w.w, acc[1][3]);
        acc[2][0] = fmaf(a.z, w.x, acc[2][0]); acc[2][1] = fmaf(a.z, w.y, acc[2][1]);
        acc[2][2] = fmaf(a.z, w.z, acc[2][2]); acc[2][3] = fmaf(a.z, w.w, acc[2][3]);
        acc[3][0] = fmaf(a.w, w.x, acc[3][0]); acc[3][1] = fmaf(a.w, w.y, acc[3][1]);
        acc[3][2] = fmaf(a.w, w.z, acc[3][2]); acc[3][3] = fmaf(a.w, w.w, acc[3][3]);
    }
    float4 asv = *(const float4*)&gat_as[widx * 128 + col];
    float4 adv = *(const float4*)&gat_ad[widx * 128 + col];
    int lane = tid & 31;
    // per-row attention dots: reduce 4 cols locally then across the warp
#pragma unroll
    for (int r = 0; r < 4; r++) {
        float ps = acc[r][0] * asv.x + acc[r][1] * asv.y
                 + acc[r][2] * asv.z + acc[r][3] * asv.w;
        float pd = acc[r][0] * adv.x + acc[r][1] * adv.y
                 + acc[r][2] * adv.z + acc[r][3] * adv.w;
#pragma unroll
        for (int o = 16; o > 0; o >>= 1) {
            ps += __shfl_down_sync(0xffffffffu, ps, o);
            pd += __shfl_down_sync(0xffffffffu, pd, o);
        }
        if (lane == 0) {
            int n = r0 + rq * 4 + r;
            g_hs[n] = ps; g_hd[n] = pd;
            float w = expf(lrelu(ps + pd));   // self-loop weight (shift-free softmax)
            g_den[n] = w;
            sws[rq * 4 + r] = w;
        }
    }
    __syncthreads();
#pragma unroll
    for (int r = 0; r < 4; r++) {
        int row = r0 + rq * 4 + r;
        float sw = sws[rq * 4 + r];
        float4 h = make_float4(acc[r][0], acc[r][1], acc[r][2], acc[r][3]);
        *(float4*)&g_h[row * 128 + col] = h;
        float4 o = make_float4(sw * h.x, sw * h.y, sw * h.z, sw * h.w);
        *(float4*)&g_o[row * 128 + col] = o;
    }
}

// per-edge: accumulate unnormalized numerator + denominator in ONE pass
__global__ void k_edge(const int* __restrict__ dei, const int* __restrict__ pei) {
    int gid = blockIdx.x * blockDim.x + threadIdx.x;
    int e = gid >> 5, lane = gid & 31;
    if (e >= ETOT) return;
    int s, d;
    if (e < E1T) { s = dei[e]; d = dei[E1T + e]; }
    else { int q = e - E1T; s = pei[q] + ND; d = pei[E2T + q] + ND; }
    float w = 0.f;
    if (lane == 0) {
        w = expf(lrelu(g_hs[s] + g_hd[d]));
        atomicAdd(&g_den[d], w);
    }
    w = __shfl_sync(0xffffffffu, w, 0);
#pragma unroll
    for (int c = 0; c < 4; c++) {
        int f = lane + 32 * c;
        atomicAdd(&g_o[d * 128 + f], w * g_h[s * 128 + f]);
    }
}

// normalize + bias + relu + residual accum; last layer also does row sums
__global__ void k_final(const float* __restrict__ gat_b, int layer) {
    int gid = blockIdx.x * blockDim.x + threadIdx.x;
    int n = gid >> 5, lane = gid & 31;
    if (n >= NODES) return;
    int widx = (n < ND ? 0 : 3) + layer;
    float inv = 1.0f / g_den[n];
    float4 o = ((const float4*)&g_o[n * 128])[lane];
    float4 b = ((const float4*)&gat_b[widx * 128])[lane];
    float4 v;
    v.x = fmaxf(fmaf(o.x, inv, b.x), 0.f);
    v.y = fmaxf(fmaf(o.y, inv, b.y), 0.f);
    v.z = fmaxf(fmaf(o.z, inv, b.z), 0.f);
    v.w = fmaxf(fmaf(o.w, inv, b.w), 0.f);
    float4* xs4 = (float4*)&g_xsum[n * 128];
    float4 sum;
    if (layer == 0) sum = v;
    else {
        float4 p = xs4[lane];
        sum.x = p.x + v.x; sum.y = p.y + v.y; sum.z = p.z + v.z; sum.w = p.w + v.w;
    }
    xs4[lane] = sum;
    if (layer < 2) ((float4*)&g_x[n * 128])[lane] = v;
    else {
        float s = sum.x + sum.y + sum.z + sum.w;
#pragma unroll
        for (int o2 = 16; o2 > 0; o2 >>= 1) s += __shfl_down_sync(0xffffffffu, s, o2);
        if (lane == 0) g_rs[n] = s * (1.f / 256.f);
    }
}

// ---------------- SE layer 1 weight reductions (parallelism-first) ----------------
// WL[i,n] = sum_j W[(i*192+j), n] ; grid (16 ncol, 79 i) = 1264 blocks
__global__ void k_wredL(const float* __restrict__ W1) {
    int n = blockIdx.x * 128 + threadIdx.x;
    if (n >= SEHID) return;
    int i = blockIdx.y;
    const float* p = W1 + (size_t)(i * 192) * SEHID + n;
    float a0 = 0.f, a1 = 0.f, a2 = 0.f, a3 = 0.f;
#pragma unroll 2
    for (int j = 0; j < 192; j += 8) {
        a0 += p[(size_t)(j+0) * SEHID] + p[(size_t)(j+4) * SEHID];
        a1 += p[(size_t)(j+1) * SEHID] + p[(size_t)(j+5) * SEHID];
        a2 += p[(size_t)(j+2) * SEHID] + p[(size_t)(j+6) * SEHID];
        a3 += p[(size_t)(j+3) * SEHID] + p[(size_t)(j+7) * SEHID];
    }
    g_sew[i * SEHID + n] = (a0 + a1) + (a2 + a3);
}
// WP[j,n] = sum_i W[(i*192+j), n] ; grid (16 ncol, 192 j) = 3072 blocks
__global__ void k_wredP(const float* __restrict__ W1) {
    int n = blockIdx.x * 128 + threadIdx.x;
    if (n >= SEHID) return;
    int j = blockIdx.y;
    const float* p = W1 + (size_t)j * SEHID + n;
    const size_t S = (size_t)192 * SEHID;
    float a0 = 0.f, a1 = 0.f, a2 = 0.f, a3 = 0.f;
    int i = 0;
#pragma unroll 2
    for (; i + 8 <= LL1; i += 8) {
        a0 += p[(i+0) * S] + p[(i+4) * S];
        a1 += p[(i+1) * S] + p[(i+5) * S];
        a2 += p[(i+2) * S] + p[(i+6) * S];
        a3 += p[(i+3) * S] + p[(i+7) * S];
    }
    for (; i < LL1; i++) a0 += p[i * S];
    g_sew[(LL1 + j) * SEHID + n] = (a0 + a1) + (a2 + a3);
}

// c1(32,2000) = [rl|rp](32,271) @ g_sew(271,2000) + b ; f32x2, row-paired
__global__ void k_se1(const float* __restrict__ bias) {
    __shared__ float AsT[SEK][36];
    int tid = threadIdx.x;
    int n = blockIdx.x * 128 + tid;
    for (int idx = tid; idx < 32 * SEK; idx += 128) {
        int m = idx / SEK, k = idx - m * SEK;
        float v = (k < LL1) ? g_rs[m * LL1 + k] : g_rs[ND + m * LL2 + (k - LL1)];
        AsT[k][m] = v;
    }
    __syncthreads();
    if (n >= SEHID) return;
    float bn = bias[n];
    unsigned long long acc[16];
    unsigned long long bp = pack2(bn, bn);
#pragma unroll
    for (int q = 0; q < 16; q++) acc[q] = bp;
    unsigned sbase = (unsigned)__cvta_generic_to_shared(&AsT[0][0]);
#pragma unroll 4
    for (int k = 0; k < SEK; k++) {
        float w = g_sew[k * SEHID + n];
        unsigned long long w2 = pack2(w, w);
        unsigned row = sbase + (unsigned)k * 144;
#pragma unroll
        for (int q = 0; q < 8; q++) {
            unsigned long long a0, a1;
            lds_v2u64(row + q * 16, a0, a1);
            fma2(acc[2 * q], a0, w2);
            fma2(acc[2 * q + 1], a1, w2);
        }
    }
#pragma unroll
    for (int q = 0; q < 16; q++) {
        float lo, hi; unpack2(acc[q], lo, hi);
        g_c1[(2 * q) * SEHID + n] = lo;
        g_c1[(2 * q + 1) * SEHID + n] = hi;
    }
}

__global__ void k_initc2(const float* __restrict__ bias) {
    int idx = blockIdx.x * blockDim.x + threadIdx.x;
    if (idx < BSZ * SEIN) g_c2[idx] = bias[idx % SEIN];
}

// c2 += relu(c1) @ se2_w ; f32x2, split-K=8 (chunks of 250)
#define TK2 50
__global__ void k_se2(const float* __restrict__ W) {
    __shared__ float AsT[TK2][36];
    int tid = threadIdx.x;
    int n = blockIdx.x * 128 + tid;
    int k0 = blockIdx.y * 250;
    bool valid = (n < SEIN);
    unsigned long long acc[16];
#pragma unroll
    for (int q = 0; q < 16; q++) acc[q] = 0ULL;
    unsigned sbase = (unsigned)__cvta_generic_to_shared(&AsT[0][0]);
    for (int kk = k0; kk < k0 + 250; kk += TK2) {
        __syncthreads();
        for (int idx = tid; idx < 32 * TK2; idx += 128) {
            int m = idx / TK2, t = idx - m * TK2;
            AsT[t][m] = fmaxf(g_c1[m * SEHID + kk + t], 0.f);
        }
        __syncthreads();
        if (valid) {
            const float* wp = W + (size_t)kk * SEIN + n;
#pragma unroll 5
            for (int t = 0; t < TK2; t++) {
                float w = wp[(size_t)t * SEIN];
                unsigned long long w2 = pack2(w, w);
                unsigned row = sbase + (unsigned)t * 144;
#pragma unroll
                for (int q = 0; q < 8; q++) {
                    unsigned long long a0, a1;
                    lds_v2u64(row + q * 16, a0, a1);
                    fma2(acc[2 * q], a0, w2);
                    fma2(acc[2 * q + 1], a1, w2);
                }
            }
        }
    }
    if (valid) {
#pragma unroll
        for (int q = 0; q < 16; q++) {
            float lo, hi; unpack2(acc[q], lo, hi);
            atomicAdd(&g_c2[(size_t)(2 * q) * SEIN + n], lo);
            atomicAdd(&g_c2[(size_t)(2 * q + 1) * SEIN + n], hi);
        }
    }
}

// sigmoid folded; wl[b,i] and wp[b,j] weighted sums
__global__ void k_wlp(const float* __restrict__ inter) {
    int gid = blockIdx.x * blockDim.x + threadIdx.x;
    int w = gid >> 5, lane = gid & 31;
    if (w < BSZ * LL1) {
        int b = w / LL1, i = w - b * LL1;
        float s = 0.f;
        for (int j = lane; j < LL2; j += 32) {
            int idx = b * SEIN + i * LL2 + j;
            float sg = 1.f / (1.f + expf(-g_c2[idx]));
            s += sg / inter[idx];
        }
#pragma unroll
        for (int o = 16; o > 0; o >>= 1) s += __shfl_down_sync(0xffffffffu, s, o);
        if (lane == 0) g_wl[w] = s * (1.f / (float)SEIN);
    } else if (w < BSZ * (LL1 + LL2)) {
        int w2i = w - BSZ * LL1;
        int b = w2i / LL2, j = w2i - b * LL2;
        float s = 0.f;
        for (int i = lane; i < LL1; i += 32) {
            int idx = b * SEIN + i * LL2 + j;
            float sg = 1.f / (1.f + expf(-g_c2[idx]));
            s += sg / inter[idx];
        }
#pragma unroll
        for (int o = 16; o > 0; o >>= 1) s += __shfl_down_sync(0xffffffffu, s, o);
        if (lane == 0) g_wp[w2i] = s * (1.f / (float)SEIN);
    }
}

__global__ void k_fuse() {
    int b = blockIdx.x, t = threadIdx.x;
    float acc = 0.f;
    if (t < HIDD) {
        for (int i = 0; i < LL1; i++)
            acc = fmaf(g_wl[b * LL1 + i], g_xsum[(b * LL1 + i) * HIDD + t], acc);
    } else {
        int h = t - HIDD;
        for (int j = 0; j < LL2; j++)
            acc = fmaf(g_wp[b * LL2 + j], g_xsum[(ND + b * LL2 + j) * HIDD + h], acc);
    }
    g_xx[b * 256 + t] = acc;
}

// ---------------- fused head MLP: one block per batch row ----------------
__global__ void __launch_bounds__(512) k_head(
    const float* __restrict__ fc1_w, const float* __restrict__ fc1_b,
    const float* __restrict__ fc2_w, const float* __restrict__ fc2_b,
    const float* __restrict__ fc3_w, const float* __restrict__ fc3_b,
    const float* __restrict__ fc4_w, const float* __restrict__ fc4_b,
    const float* __restrict__ out_w, const float* __restrict__ out_b,
    float* __restrict__ dout) {
    int b = blockIdx.x, t = threadIdx.x;
    __shared__ float s0[256], s1[512], s2[256], s3[128], s4[64];
    if (t < 256) s0[t] = g_xx[b * 256 + t];
    __syncthreads();
    // fc1: 256 -> 512 (h1 pre-relu is an output)
    {
        float acc = fc1_b[t];
        for (int k = 0; k < 256; k++) acc = fmaf(s0[k], fc1_w[k * 512 + t], acc);
        dout[32 + b * 512 + t] = acc;
        s1[t] = fmaxf(acc, 0.f);
    }
    __syncthreads();
    // fc2: 512 -> 256
    if (t < 256) {
        float acc = fc2_b[t];
        for (int k = 0; k < 512; k++) acc = fmaf(s1[k], fc2_w[k * 256 + t], acc);
        s2[t] = fmaxf(acc, 0.f);
    }
    __syncthreads();
    // fc3: 256 -> 128
    if (t < 128) {
        float acc = fc3_b[t];
        for (int k = 0; k < 256; k++) acc = fmaf(s2[k], fc3_w[k * 128 + t], acc);
        s3[t] = fmaxf(acc, 0.f);
    }
    __syncthreads();
    // fc4: 128 -> 64
    if (t < 64) {
        float acc = fc4_b[t];
        for (int k = 0; k < 128; k++) acc = fmaf(s3[k], fc4_w[k * 64 + t], acc);
        s4[t] = fmaxf(acc, 0.f);
    }
    __syncthreads();
    // out: 64 -> 1
    if (t < 32) {
        float acc = s4[t] * out_w[t] + s4[t + 32] * out_w[t + 32];
#pragma unroll
        for (int o = 16; o > 0; o >>= 1) acc += __shfl_down_sync(0xffffffffu, acc, o);
        if (t == 0) dout[b] = acc + out_b[0];
    }
}

extern "C" void kernel_launch(void* const* d_in, const int* in_sizes, int n_in,
                              void* d_out, int out_size) {
    const float* x1    = (const float*)d_in[0];
    const float* x2    = (const float*)d_in[1];
    const float* inter = (const float*)d_in[2];
    const int*   dei   = (const int*)d_in[3];
    const int*   pei   = (const int*)d_in[4];
    const float* w1    = (const float*)d_in[5];
    const float* b1    = (const float*)d_in[6];
    const float* w2    = (const float*)d_in[7];
    const float* b2    = (const float*)d_in[8];
    const float* gat_w = (const float*)d_in[9];
    const float* gat_as= (const float*)d_in[10];
    const float* gat_ad= (const float*)d_in[11];
    const float* gat_b = (const float*)d_in[12];
    const float* se1_w = (const float*)d_in[13];
    const float* se1_b = (const float*)d_in[14];
    const float* se2_w = (const float*)d_in[15];
    const float* se2_b = (const float*)d_in[16];
    const float* fc1_w = (const float*)d_in[17];
    const float* fc1_b = (const float*)d_in[18];
    const float* fc2_w = (const float*)d_in[19];
    const float* fc2_b = (const float*)d_in[20];
    const float* fc3_w = (const float*)d_in[21];
    const float* fc3_b = (const float*)d_in[22];
    const float* fc4_w = (const float*)d_in[23];
    const float* fc4_b = (const float*)d_in[24];
    const float* out_w = (const float*)d_in[25];
    const float* out_b = (const float*)d_in[26];
    float* dout = (float*)d_out;

    k_embed<<<NODES / 8, 128>>>(x1, x2, w1, b1, w2, b2);

    for (int l = 0; l < 3; l++) {
        k_gat_h<<<NODES / 16, 128>>>(gat_w, gat_as, gat_ad, l);
        k_edge<<<(ETOT * 32 + 255) / 256, 256>>>(dei, pei);
        k_final<<<(NODES * 32 + 255) / 256, 256>>>(gat_b, l);
    }

    k_wredL<<<dim3(16, LL1), 128>>>(se1_w);
    k_wredP<<<dim3(16, LL2), 128>>>(se1_w);
    k_se1<<<16, 128>>>(se1_b);

    k_initc2<<<(BSZ * SEIN + 255) / 256, 256>>>(se2_b);
    k_se2<<<dim3(119, 8), 128>>>(se2_w);

    k_wlp<<<(BSZ * (LL1 + LL2) * 32 + 255) / 256, 256>>>(inter);
    k_fuse<<<BSZ, 256>>>();

    k_head<<<BSZ, 512>>>(fc1_w, fc1_b, fc2_w, fc2_b, fc3_w, fc3_b,
                         fc4_w, fc4_b, out_w, out_b, dout);
}

// round 14
// speedup vs baseline: 1.9547x; 1.3416x over previous
#include <cuda_runtime.h>
#include <math.h>

#define NODES 8672
#define ND    2528
#define HIDD  128
#define BSZ   32
#define LL1   79
#define LL2   192
#define E1T   5120
#define E2T   12800
#define ETOT  17920
#define SEIN  15168
#define SEHID 2000
#define SEK   271      // 79 + 192

// mega-launch block ranges
#define NB_GAT   1084
#define NB_WREDL 1264          // 16 ncol x 79 i
#define NB_WREDP 3072          // 16 ncol x 192 j
#define NB_ZC1   500           // 64000 / 128
#define NB_BC2   3792          // 485376 / 128
#define NB_TOTAL (NB_GAT + NB_WREDL + NB_WREDP + NB_ZC1 + NB_BC2)

// ---------------- device scratch ----------------
__device__ float g_x   [NODES*HIDD];
__device__ float g_h   [NODES*HIDD];
__device__ float g_o   [NODES*HIDD];     // unnormalized numerator
__device__ float g_xsum[NODES*HIDD];
__device__ float g_hs[NODES], g_hd[NODES], g_den[NODES];
__device__ float g_rs[NODES];            // row sums / 256
__device__ float g_sew[SEK*SEHID];       // [0:79) WL rows, [79:271) WP rows
__device__ float g_c1[BSZ*SEHID];
__device__ float g_c2[BSZ*SEIN];
__device__ float g_wl[BSZ*LL1], g_wp[BSZ*LL2];
__device__ float g_xx[BSZ*256];

__device__ __forceinline__ float lrelu(float x) { return x > 0.f ? x : 0.2f * x; }

// ---- f32x2 helpers ----
__device__ __forceinline__ void fma2(unsigned long long& d, unsigned long long a, unsigned long long b) {
    asm("fma.rn.f32x2 %0, %1, %2, %0;" : "+l"(d) : "l"(a), "l"(b));
}
__device__ __forceinline__ unsigned long long pack2(float x, float y) {
    unsigned long long r;
    asm("mov.b64 %0, {%1, %2};" : "=l"(r) : "f"(x), "f"(y));
    return r;
}
__device__ __forceinline__ void unpack2(unsigned long long v, float& x, float& y) {
    asm("mov.b64 {%0, %1}, %2;" : "=f"(x), "=f"(y) : "l"(v));
}
__device__ __forceinline__ void lds_v2u64(unsigned saddr, unsigned long long& a, unsigned long long& b) {
    asm volatile("ld.shared.v2.u64 {%0,%1}, [%2];" : "=l"(a), "=l"(b) : "r"(saddr));
}

// ---------------- fused embedding MLP (8 rows / block) ----------------
__global__ void k_embed(const float* __restrict__ x1, const float* __restrict__ x2,
                        const float* __restrict__ w1, const float* __restrict__ b1,
                        const float* __restrict__ w2, const float* __restrict__ b2) {
    __shared__ float xsT[52][8];
    __shared__ float hbT[128][8];
    int tid = threadIdx.x;
    int r0 = blockIdx.x * 8;
    for (int idx = tid; idx < 8 * 52; idx += 128) {
        int r = idx / 52, c = idx - r * 52;
        int row = r0 + r;
        xsT[c][r] = (row < ND) ? x1[row * 52 + c] : x2[(row - ND) * 52 + c];
    }
    __syncthreads();
    float acc[8] = {0.f,0.f,0.f,0.f,0.f,0.f,0.f,0.f};
    for (int k = 0; k < 52; k++) {
        float w = w1[k * 128 + tid];
        float4 a0 = *(const float4*)&xsT[k][0];
        float4 a1 = *(const float4*)&xsT[k][4];
        acc[0] = fmaf(a0.x, w, acc[0]); acc[1] = fmaf(a0.y, w, acc[1]);
        acc[2] = fmaf(a0.z, w, acc[2]); acc[3] = fmaf(a0.w, w, acc[3]);
        acc[4] = fmaf(a1.x, w, acc[4]); acc[5] = fmaf(a1.y, w, acc[5]);
        acc[6] = fmaf(a1.z, w, acc[6]); acc[7] = fmaf(a1.w, w, acc[7]);
    }
    float bv = b1[tid];
#pragma unroll
    for (int r = 0; r < 8; r++) hbT[tid][r] = fmaxf(acc[r] + bv, 0.f);
    __syncthreads();
    float a2[8] = {0.f,0.f,0.f,0.f,0.f,0.f,0.f,0.f};
    for (int k = 0; k < 128; k++) {
        float w = w2[k * 128 + tid];
        float4 a0 = *(const float4*)&hbT[k][0];
        float4 a1 = *(const float4*)&hbT[k][4];
        a2[0] = fmaf(a0.x, w, a2[0]); a2[1] = fmaf(a0.y, w, a2[1]);
        a2[2] = fmaf(a0.z, w, a2[2]); a2[3] = fmaf(a0.w, w, a2[3]);
        a2[4] = fmaf(a1.x, w, a2[4]); a2[5] = fmaf(a1.y, w, a2[5]);
        a2[6] = fmaf(a1.z, w, a2[6]); a2[7] = fmaf(a1.w, w, a2[7]);
    }
    float b2v = b2[tid];
#pragma unroll
    for (int r = 0; r < 8; r++)
        g_x[(r0 + r) * 128 + tid] = fmaxf(a2[r] + b2v, 0.f);
}

// ---------------- GAT GEMM body (8 rows / block, tid = output col) --------
__device__ __forceinline__ void gat_body(int bx, const float* __restrict__ gat_w,
                                         const float* __restrict__ gat_as,
                                         const float* __restrict__ gat_ad, int layer) {
    __shared__ float xsT[128][8];
    __shared__ float redS[8][4], redD[8][4];
    __shared__ float sws[8];
    int tid = threadIdx.x;
    int r0 = bx * 8;
    for (int idx = tid; idx < 1024; idx += 128) {
        int r = idx >> 7, k = idx & 127;
        xsT[k][r] = g_x[(r0 + r) * 128 + k];
    }
    __syncthreads();
    int widx = (r0 < ND ? 0 : 3) + layer;
    const float* W = gat_w + (size_t)widx * 16384;
    float acc[8] = {0.f,0.f,0.f,0.f,0.f,0.f,0.f,0.f};
    for (int k = 0; k < 128; k++) {
        float w = W[k * 128 + tid];
        float4 a0 = *(const float4*)&xsT[k][0];
        float4 a1 = *(const float4*)&xsT[k][4];
        acc[0] = fmaf(a0.x, w, acc[0]); acc[1] = fmaf(a0.y, w, acc[1]);
        acc[2] = fmaf(a0.z, w, acc[2]); acc[3] = fmaf(a0.w, w, acc[3]);
        acc[4] = fmaf(a1.x, w, acc[4]); acc[5] = fmaf(a1.y, w, acc[5]);
        acc[6] = fmaf(a1.z, w, acc[6]); acc[7] = fmaf(a1.w, w, acc[7]);
    }
    float asv = gat_as[widx * 128 + tid], adv = gat_ad[widx * 128 + tid];
    int lane = tid & 31, wrp = tid >> 5;
#pragma unroll
    for (int r = 0; r < 8; r++) {
        float ps = acc[r] * asv, pd = acc[r] * adv;
#pragma unroll
        for (int o = 16; o > 0; o >>= 1) {
            ps += __shfl_down_sync(0xffffffffu, ps, o);
            pd += __shfl_down_sync(0xffffffffu, pd, o);
        }
        if (lane == 0) { redS[r][wrp] = ps; redD[r][wrp] = pd; }
    }
    __syncthreads();
    if (tid < 8) {
        float hs = redS[tid][0] + redS[tid][1] + redS[tid][2] + redS[tid][3];
        float hd = redD[tid][0] + redD[tid][1] + redD[tid][2] + redD[tid][3];
        g_hs[r0 + tid] = hs; g_hd[r0 + tid] = hd;
        float w = expf(lrelu(hs + hd));   // self-loop weight (shift-free softmax)
        g_den[r0 + tid] = w;
        sws[tid] = w;
    }
    __syncthreads();
#pragma unroll
    for (int r = 0; r < 8; r++) {
        g_h[(r0 + r) * 128 + tid] = acc[r];
        g_o[(r0 + r) * 128 + tid] = sws[r] * acc[r];
    }
}

__global__ void __launch_bounds__(128) k_gat_h(
        const float* __restrict__ gat_w, const float* __restrict__ gat_as,
        const float* __restrict__ gat_ad, int layer) {
    gat_body(blockIdx.x, gat_w, gat_as, gat_ad, layer);
}

// ---------------- mega layer-0 launch: gat l0 + wredL + wredP + inits ------
__global__ void __launch_bounds__(128) k_l0(
        const float* __restrict__ gat_w, const float* __restrict__ gat_as,
        const float* __restrict__ gat_ad, const float* __restrict__ W1,
        const float* __restrict__ se2_b) {
    int bx = blockIdx.x;
    int tid = threadIdx.x;
    if (bx < NB_GAT) {
        gat_body(bx, gat_w, gat_as, gat_ad, 0);
        return;
    }
    bx -= NB_GAT;
    if (bx < NB_WREDL) {
        // WL[i,n] = sum_j W[(i*192+j), n]
        int n = (bx & 15) * 128 + tid;
        if (n >= SEHID) return;
        int i = bx >> 4;
        const float* p = W1 + (size_t)(i * 192) * SEHID + n;
        float a0 = 0.f, a1 = 0.f, a2 = 0.f, a3 = 0.f;
#pragma unroll 2
        for (int j = 0; j < 192; j += 8) {
            a0 += p[(size_t)(j+0) * SEHID] + p[(size_t)(j+4) * SEHID];
            a1 += p[(size_t)(j+1) * SEHID] + p[(size_t)(j+5) * SEHID];
            a2 += p[(size_t)(j+2) * SEHID] + p[(size_t)(j+6) * SEHID];
            a3 += p[(size_t)(j+3) * SEHID] + p[(size_t)(j+7) * SEHID];
        }
        g_sew[i * SEHID + n] = (a0 + a1) + (a2 + a3);
        return;
    }
    bx -= NB_WREDL;
    if (bx < NB_WREDP) {
        // WP[j,n] = sum_i W[(i*192+j), n]
        int n = (bx & 15) * 128 + tid;
        if (n >= SEHID) return;
        int j = bx >> 4;
        const float* p = W1 + (size_t)j * SEHID + n;
        const size_t S = (size_t)192 * SEHID;
        float a0 = 0.f, a1 = 0.f, a2 = 0.f, a3 = 0.f;
        int i = 0;
#pragma unroll 2
        for (; i + 8 <= LL1; i += 8) {
            a0 += p[(i+0) * S] + p[(i+4) * S];
            a1 += p[(i+1) * S] + p[(i+5) * S];
            a2 += p[(i+2) * S] + p[(i+6) * S];
            a3 += p[(i+3) * S] + p[(i+7) * S];
        }
        for (; i < LL1; i++) a0 += p[i * S];
        g_sew[(LL1 + j) * SEHID + n] = (a0 + a1) + (a2 + a3);
        return;
    }
    bx -= NB_WREDP;
    if (bx < NB_ZC1) {
        int idx = bx * 128 + tid;
        if (idx < BSZ * SEHID) g_c1[idx] = 0.f;
        return;
    }
    bx -= NB_ZC1;
    {
        int idx = bx * 128 + tid;
        if (idx < BSZ * SEIN) g_c2[idx] = se2_b[idx % SEIN];
    }
}

// per-edge: accumulate unnormalized numerator + denominator in ONE pass
__global__ void k_edge(const int* __restrict__ dei, const int* __restrict__ pei) {
    int gid = blockIdx.x * blockDim.x + threadIdx.x;
    int e = gid >> 5, lane = gid & 31;
    if (e >= ETOT) return;
    int s, d;
    if (e < E1T) { s = dei[e]; d = dei[E1T + e]; }
    else { int q = e - E1T; s = pei[q] + ND; d = pei[E2T + q] + ND; }
    float w = 0.f;
    if (lane == 0) {
        w = expf(lrelu(g_hs[s] + g_hd[d]));
        atomicAdd(&g_den[d], w);
    }
    w = __shfl_sync(0xffffffffu, w, 0);
#pragma unroll
    for (int c = 0; c < 4; c++) {
        int f = lane + 32 * c;
        atomicAdd(&g_o[d * 128 + f], w * g_h[s * 128 + f]);
    }
}

// normalize + bias + relu + residual accum; last layer also does row sums
__global__ void k_final(const float* __restrict__ gat_b, int layer) {
    int gid = blockIdx.x * blockDim.x + threadIdx.x;
    int n = gid >> 5, lane = gid & 31;
    if (n >= NODES) return;
    int widx = (n < ND ? 0 : 3) + layer;
    float inv = 1.0f / g_den[n];
    float4 o = ((const float4*)&g_o[n * 128])[lane];
    float4 b = ((const float4*)&gat_b[widx * 128])[lane];
    float4 v;
    v.x = fmaxf(fmaf(o.x, inv, b.x), 0.f);
    v.y = fmaxf(fmaf(o.y, inv, b.y), 0.f);
    v.z = fmaxf(fmaf(o.z, inv, b.z), 0.f);
    v.w = fmaxf(fmaf(o.w, inv, b.w), 0.f);
    float4* xs4 = (float4*)&g_xsum[n * 128];
    float4 sum;
    if (layer == 0) sum = v;
    else {
        float4 p = xs4[lane];
        sum.x = p.x + v.x; sum.y = p.y + v.y; sum.z = p.z + v.z; sum.w = p.w + v.w;
    }
    xs4[lane] = sum;
    if (layer < 2) ((float4*)&g_x[n * 128])[lane] = v;
    else {
        float s = sum.x + sum.y + sum.z + sum.w;
#pragma unroll
        for (int o2 = 16; o2 > 0; o2 >>= 1) s += __shfl_down_sync(0xffffffffu, s, o2);
        if (lane == 0) g_rs[n] = s * (1.f / 256.f);
    }
}

// c1(32,2000) += [rl|rp](32, chunk of 271) @ g_sew + b ; split-K=4
__global__ void k_se1(const float* __restrict__ bias) {
    __shared__ float AsT[68][36];
    int tid = threadIdx.x;
    int n = blockIdx.x * 128 + tid;
    int k0 = blockIdx.y * 68;
    int k1 = min(SEK, k0 + 68);
    int klen = k1 - k0;
    for (int idx = tid; idx < 32 * klen; idx += 128) {
        int m = idx / klen, kk = idx - m * klen;
        int k = k0 + kk;
        float v = (k < LL1) ? g_rs[m * LL1 + k] : g_rs[ND + m * LL2 + (k - LL1)];
        AsT[kk][m] = v;
    }
    __syncthreads();
    if (n >= SEHID) return;
    unsigned long long acc[16];
    if (blockIdx.y == 0) {
        float bn = bias[n];
        unsigned long long bp = pack2(bn, bn);
#pragma unroll
        for (int q = 0; q < 16; q++) acc[q] = bp;
    } else {
#pragma unroll
        for (int q = 0; q < 16; q++) acc[q] = 0ULL;
    }
    unsigned sbase = (unsigned)__cvta_generic_to_shared(&AsT[0][0]);
#pragma unroll 4
    for (int kk = 0; kk < klen; kk++) {
        float w = g_sew[(k0 + kk) * SEHID + n];
        unsigned long long w2 = pack2(w, w);
        unsigned row = sbase + (unsigned)kk * 144;
#pragma unroll
        for (int q = 0; q < 8; q++) {
            unsigned long long a0, a1;
            lds_v2u64(row + q * 16, a0, a1);
            fma2(acc[2 * q], a0, w2);
            fma2(acc[2 * q + 1], a1, w2);
        }
    }
#pragma unroll
    for (int q = 0; q < 16; q++) {
        float lo, hi; unpack2(acc[q], lo, hi);
        atomicAdd(&g_c1[(2 * q) * SEHID + n], lo);
        atomicAdd(&g_c1[(2 * q + 1) * SEHID + n], hi);
    }
}

// c2 += relu(c1) @ se2_w ; f32x2, split-K=8 (chunks of 250)
#define TK2 50
__global__ void k_se2(const float* __restrict__ W) {
    __shared__ float AsT[TK2][36];
    int tid = threadIdx.x;
    int n = blockIdx.x * 128 + tid;
    int k0 = blockIdx.y * 250;
    bool valid = (n < SEIN);
    unsigned long long acc[16];
#pragma unroll
    for (int q = 0; q < 16; q++) acc[q] = 0ULL;
    unsigned sbase = (unsigned)__cvta_generic_to_shared(&AsT[0][0]);
    for (int kk = k0; kk < k0 + 250; kk += TK2) {
        __syncthreads();
        for (int idx = tid; idx < 32 * TK2; idx += 128) {
            int m = idx / TK2, t = idx - m * TK2;
            AsT[t][m] = fmaxf(g_c1[m * SEHID + kk + t], 0.f);
        }
        __syncthreads();
        if (valid) {
            const float* wp = W + (size_t)kk * SEIN + n;
#pragma unroll 5
            for (int t = 0; t < TK2; t++) {
                float w = wp[(size_t)t * SEIN];
                unsigned long long w2 = pack2(w, w);
                unsigned row = sbase + (unsigned)t * 144;
#pragma unroll
                for (int q = 0; q < 8; q++) {
                    unsigned long long a0, a1;
                    lds_v2u64(row + q * 16, a0, a1);
                    fma2(acc[2 * q], a0, w2);
                    fma2(acc[2 * q + 1], a1, w2);
                }
            }
        }
    }
    if (valid) {
#pragma unroll
        for (int q = 0; q < 16; q++) {
            float lo, hi; unpack2(acc[q], lo, hi);
            atomicAdd(&g_c2[(size_t)(2 * q) * SEIN + n], lo);
            atomicAdd(&g_c2[(size_t)(2 * q + 1) * SEIN + n], hi);
        }
    }
}

// sigmoid folded; wl[b,i] and wp[b,j] weighted sums
__global__ void k_wlp(const float* __restrict__ inter) {
    int gid = blockIdx.x * blockDim.x + threadIdx.x;
    int w = gid >> 5, lane = gid & 31;
    if (w < BSZ * LL1) {
        int b = w / LL1, i = w - b * LL1;
        float s = 0.f;
        for (int j = lane; j < LL2; j += 32) {
            int idx = b * SEIN + i * LL2 + j;
            float sg = 1.f / (1.f + expf(-g_c2[idx]));
            s += sg / inter[idx];
        }
#pragma unroll
        for (int o = 16; o > 0; o >>= 1) s += __shfl_down_sync(0xffffffffu, s, o);
        if (lane == 0) g_wl[w] = s * (1.f / (float)SEIN);
    } else if (w < BSZ * (LL1 + LL2)) {
        int w2i = w - BSZ * LL1;
        int b = w2i / LL2, j = w2i - b * LL2;
        float s = 0.f;
        for (int i = lane; i < LL1; i += 32) {
            int idx = b * SEIN + i * LL2 + j;
            float sg = 1.f / (1.f + expf(-g_c2[idx]));
            s += sg / inter[idx];
        }
#pragma unroll
        for (int o = 16; o > 0; o >>= 1) s += __shfl_down_sync(0xffffffffu, s, o);
        if (lane == 0) g_wp[w2i] = s * (1.f / (float)SEIN);
    }
}

__global__ void k_fuse() {
    int b = blockIdx.x, t = threadIdx.x;
    float acc = 0.f;
    if (t < HIDD) {
        for (int i = 0; i < LL1; i++)
            acc = fmaf(g_wl[b * LL1 + i], g_xsum[(b * LL1 + i) * HIDD + t], acc);
    } else {
        int h = t - HIDD;
        for (int j = 0; j < LL2; j++)
            acc = fmaf(g_wp[b * LL2 + j], g_xsum[(ND + b * LL2 + j) * HIDD + h], acc);
    }
    g_xx[b * 256 + t] = acc;
}

// ---------------- fused head MLP: one block per batch row ----------------
__global__ void __launch_bounds__(512) k_head(
    const float* __restrict__ fc1_w, const float* __restrict__ fc1_b,
    const float* __restrict__ fc2_w, const float* __restrict__ fc2_b,
    const float* __restrict__ fc3_w, const float* __restrict__ fc3_b,
    const float* __restrict__ fc4_w, const float* __restrict__ fc4_b,
    const float* __restrict__ out_w, const float* __restrict__ out_b,
    float* __restrict__ dout) {
    int b = blockIdx.x, t = threadIdx.x;
    __shared__ float s0[256], s1[512], s2[256], s3[128], s4[64];
    if (t < 256) s0[t] = g_xx[b * 256 + t];
    __syncthreads();
    // fc1: 256 -> 512 (h1 pre-relu is an output)
    {
        float acc = fc1_b[t];
        for (int k = 0; k < 256; k++) acc = fmaf(s0[k], fc1_w[k * 512 + t], acc);
        dout[32 + b * 512 + t] = acc;
        s1[t] = fmaxf(acc, 0.f);
    }
    __syncthreads();
    // fc2: 512 -> 256
    if (t < 256) {
        float acc = fc2_b[t];
        for (int k = 0; k < 512; k++) acc = fmaf(s1[k], fc2_w[k * 256 + t], acc);
        s2[t] = fmaxf(acc, 0.f);
    }
    __syncthreads();
    // fc3: 256 -> 128
    if (t < 128) {
        float acc = fc3_b[t];
        for (int k = 0; k < 256; k++) acc = fmaf(s2[k], fc3_w[k * 128 + t], acc);
        s3[t] = fmaxf(acc, 0.f);
    }
    __syncthreads();
    // fc4: 128 -> 64
    if (t < 64) {
        float acc = fc4_b[t];
        for (int k = 0; k < 128; k++) acc = fmaf(s3[k], fc4_w[k * 64 + t], acc);
        s4[t] = fmaxf(acc, 0.f);
    }
    __syncthreads();
    // out: 64 -> 1
    if (t < 32) {
        float acc = s4[t] * out_w[t] + s4[t + 32] * out_w[t + 32];
#pragma unroll
        for (int o = 16; o > 0; o >>= 1) acc += __shfl_down_sync(0xffffffffu, acc, o);
        if (t == 0) dout[b] = acc + out_b[0];
    }
}

extern "C" void kernel_launch(void* const* d_in, const int* in_sizes, int n_in,
                              void* d_out, int out_size) {
    const float* x1    = (const float*)d_in[0];
    const float* x2    = (const float*)d_in[1];
    const float* inter = (const float*)d_in[2];
    const int*   dei   = (const int*)d_in[3];
    const int*   pei   = (const int*)d_in[4];
    const float* w1    = (const float*)d_in[5];
    const float* b1    = (const float*)d_in[6];
    const float* w2    = (const float*)d_in[7];
    const float* b2    = (const float*)d_in[8];
    const float* gat_w = (const float*)d_in[9];
    const float* gat_as= (const float*)d_in[10];
    const float* gat_ad= (const float*)d_in[11];
    const float* gat_b = (const float*)d_in[12];
    const float* se1_w = (const float*)d_in[13];
    const float* se1_b = (const float*)d_in[14];
    const float* se2_w = (const float*)d_in[15];
    const float* se2_b = (const float*)d_in[16];
    const float* fc1_w = (const float*)d_in[17];
    const float* fc1_b = (const float*)d_in[18];
    const float* fc2_w = (const float*)d_in[19];
    const float* fc2_b = (const float*)d_in[20];
    const float* fc3_w = (const float*)d_in[21];
    const float* fc3_b = (const float*)d_in[22];
    const float* fc4_w = (const float*)d_in[23];
    const float* fc4_b = (const float*)d_in[24];
    const float* out_w = (const float*)d_in[25];
    const float* out_b = (const float*)d_in[26];
    float* dout = (float*)d_out;

    k_embed<<<NODES / 8, 128>>>(x1, x2, w1, b1, w2, b2);

    // layer 0: GAT GEMM + (overlapped) se1_w reductions + c1/c2 inits
    k_l0<<<NB_TOTAL, 128>>>(gat_w, gat_as, gat_ad, se1_w, se2_b);
    k_edge<<<(ETOT * 32 + 255) / 256, 256>>>(dei, pei);
    k_final<<<(NODES * 32 + 255) / 256, 256>>>(gat_b, 0);

    for (int l = 1; l < 3; l++) {
        k_gat_h<<<NODES / 8, 128>>>(gat_w, gat_as, gat_ad, l);
        k_edge<<<(ETOT * 32 + 255) / 256, 256>>>(dei, pei);
        k_final<<<(NODES * 32 + 255) / 256, 256>>>(gat_b, l);
    }

    k_se1<<<dim3(16, 4), 128>>>(se1_b);
    k_se2<<<dim3(119, 8), 128>>>(se2_w);

    k_wlp<<<(BSZ * (LL1 + LL2) * 32 + 255) / 256, 256>>>(inter);
    k_fuse<<<BSZ, 256>>>();

    k_head<<<BSZ, 512>>>(fc1_w, fc1_b, fc2_w, fc2_b, fc3_w, fc3_b,
                         fc4_w, fc4_b, out_w, out_b, dout);
}

// round 15
// speedup vs baseline: 2.0640x; 1.0559x over previous
#include <cuda_runtime.h>
#include <math.h>

#define NODES 8672
#define ND    2528
#define HIDD  128
#define BSZ   32
#define LL1   79
#define LL2   192
#define E1T   5120
#define E2T   12800
#define ETOT  17920
#define SEIN  15168
#define SEHID 2000
#define SEK   271      // 79 + 192

// mega-launch block ranges
#define NB_GAT   1084
#define NB_WREDL 1264          // 16 ncol x 79 i
#define NB_WREDP 3072          // 16 ncol x 192 j
#define NB_ZC1   500           // 64000 / 128
#define NB_BC2   3792          // 485376 / 128
#define NB_TOTAL (NB_GAT + NB_WREDL + NB_WREDP + NB_ZC1 + NB_BC2)

// ---------------- device scratch ----------------
__device__ float g_x   [NODES*HIDD];
__device__ float g_h   [NODES*HIDD];
__device__ float g_o   [NODES*HIDD];     // unnormalized numerator
__device__ float g_xsum[NODES*HIDD];
__device__ float g_hs[NODES], g_hd[NODES], g_den[NODES];
__device__ float g_rs[NODES];            // row sums / 256
__device__ float g_sew[SEK*SEHID];       // [0:79) WL rows, [79:271) WP rows
__device__ float g_c1[BSZ*SEHID];
__device__ float g_c2[BSZ*SEIN];
__device__ float g_wl[BSZ*LL1], g_wp[BSZ*LL2];
__device__ float g_xx[BSZ*256];

__device__ __forceinline__ float lrelu(float x) { return x > 0.f ? x : 0.2f * x; }

// ---- f32x2 helpers ----
__device__ __forceinline__ void fma2(unsigned long long& d, unsigned long long a, unsigned long long b) {
    asm("fma.rn.f32x2 %0, %1, %2, %0;" : "+l"(d) : "l"(a), "l"(b));
}
__device__ __forceinline__ unsigned long long pack2(float x, float y) {
    unsigned long long r;
    asm("mov.b64 %0, {%1, %2};" : "=l"(r) : "f"(x), "f"(y));
    return r;
}
__device__ __forceinline__ void unpack2(unsigned long long v, float& x, float& y) {
    asm("mov.b64 {%0, %1}, %2;" : "=f"(x), "=f"(y) : "l"(v));
}
__device__ __forceinline__ void lds_v2u64(unsigned saddr, unsigned long long& a, unsigned long long& b) {
    asm volatile("ld.shared.v2.u64 {%0,%1}, [%2];" : "=l"(a), "=l"(b) : "r"(saddr));
}

// ---------------- fused embedding MLP (8 rows / block) ----------------
__global__ void k_embed(const float* __restrict__ x1, const float* __restrict__ x2,
                        const float* __restrict__ w1, const float* __restrict__ b1,
                        const float* __restrict__ w2, const float* __restrict__ b2) {
    __shared__ float xsT[52][8];
    __shared__ float hbT[128][8];
    int tid = threadIdx.x;
    int r0 = blockIdx.x * 8;
    for (int idx = tid; idx < 8 * 52; idx += 128) {
        int r = idx / 52, c = idx - r * 52;
        int row = r0 + r;
        xsT[c][r] = (row < ND) ? x1[row * 52 + c] : x2[(row - ND) * 52 + c];
    }
    __syncthreads();
    float acc[8] = {0.f,0.f,0.f,0.f,0.f,0.f,0.f,0.f};
    for (int k = 0; k < 52; k++) {
        float w = w1[k * 128 + tid];
        float4 a0 = *(const float4*)&xsT[k][0];
        float4 a1 = *(const float4*)&xsT[k][4];
        acc[0] = fmaf(a0.x, w, acc[0]); acc[1] = fmaf(a0.y, w, acc[1]);
        acc[2] = fmaf(a0.z, w, acc[2]); acc[3] = fmaf(a0.w, w, acc[3]);
        acc[4] = fmaf(a1.x, w, acc[4]); acc[5] = fmaf(a1.y, w, acc[5]);
        acc[6] = fmaf(a1.z, w, acc[6]); acc[7] = fmaf(a1.w, w, acc[7]);
    }
    float bv = b1[tid];
#pragma unroll
    for (int r = 0; r < 8; r++) hbT[tid][r] = fmaxf(acc[r] + bv, 0.f);
    __syncthreads();
    float a2[8] = {0.f,0.f,0.f,0.f,0.f,0.f,0.f,0.f};
    for (int k = 0; k < 128; k++) {
        float w = w2[k * 128 + tid];
        float4 a0 = *(const float4*)&hbT[k][0];
        float4 a1 = *(const float4*)&hbT[k][4];
        a2[0] = fmaf(a0.x, w, a2[0]); a2[1] = fmaf(a0.y, w, a2[1]);
        a2[2] = fmaf(a0.z, w, a2[2]); a2[3] = fmaf(a0.w, w, a2[3]);
        a2[4] = fmaf(a1.x, w, a2[4]); a2[5] = fmaf(a1.y, w, a2[5]);
        a2[6] = fmaf(a1.z, w, a2[6]); a2[7] = fmaf(a1.w, w, a2[7]);
    }
    float b2v = b2[tid];
#pragma unroll
    for (int r = 0; r < 8; r++)
        g_x[(r0 + r) * 128 + tid] = fmaxf(a2[r] + b2v, 0.f);
}

// ---------------- GAT GEMM body (8 rows / block, tid = output col) --------
__device__ __forceinline__ void gat_body(int bx, const float* __restrict__ gat_w,
                                         const float* __restrict__ gat_as,
                                         const float* __restrict__ gat_ad, int layer) {
    __shared__ float xsT[128][8];
    __shared__ float redS[8][4], redD[8][4];
    __shared__ float sws[8];
    int tid = threadIdx.x;
    int r0 = bx * 8;
    for (int idx = tid; idx < 1024; idx += 128) {
        int r = idx >> 7, k = idx & 127;
        xsT[k][r] = g_x[(r0 + r) * 128 + k];
    }
    __syncthreads();
    int widx = (r0 < ND ? 0 : 3) + layer;
    const float* W = gat_w + (size_t)widx * 16384;
    float acc[8] = {0.f,0.f,0.f,0.f,0.f,0.f,0.f,0.f};
#pragma unroll 8
    for (int k = 0; k < 128; k++) {
        float w = W[k * 128 + tid];
        float4 a0 = *(const float4*)&xsT[k][0];
        float4 a1 = *(const float4*)&xsT[k][4];
        acc[0] = fmaf(a0.x, w, acc[0]); acc[1] = fmaf(a0.y, w, acc[1]);
        acc[2] = fmaf(a0.z, w, acc[2]); acc[3] = fmaf(a0.w, w, acc[3]);
        acc[4] = fmaf(a1.x, w, acc[4]); acc[5] = fmaf(a1.y, w, acc[5]);
        acc[6] = fmaf(a1.z, w, acc[6]); acc[7] = fmaf(a1.w, w, acc[7]);
    }
    float asv = gat_as[widx * 128 + tid], adv = gat_ad[widx * 128 + tid];
    int lane = tid & 31, wrp = tid >> 5;
#pragma unroll
    for (int r = 0; r < 8; r++) {
        float ps = acc[r] * asv, pd = acc[r] * adv;
#pragma unroll
        for (int o = 16; o > 0; o >>= 1) {
            ps += __shfl_down_sync(0xffffffffu, ps, o);
            pd += __shfl_down_sync(0xffffffffu, pd, o);
        }
        if (lane == 0) { redS[r][wrp] = ps; redD[r][wrp] = pd; }
    }
    __syncthreads();
    if (tid < 8) {
        float hs = redS[tid][0] + redS[tid][1] + redS[tid][2] + redS[tid][3];
        float hd = redD[tid][0] + redD[tid][1] + redD[tid][2] + redD[tid][3];
        g_hs[r0 + tid] = hs; g_hd[r0 + tid] = hd;
        float w = expf(lrelu(hs + hd));   // self-loop weight (shift-free softmax)
        g_den[r0 + tid] = w;
        sws[tid] = w;
    }
    __syncthreads();
#pragma unroll
    for (int r = 0; r < 8; r++) {
        g_h[(r0 + r) * 128 + tid] = acc[r];
        g_o[(r0 + r) * 128 + tid] = sws[r] * acc[r];
    }
}

__global__ void __launch_bounds__(128) k_gat_h(
        const float* __restrict__ gat_w, const float* __restrict__ gat_as,
        const float* __restrict__ gat_ad, int layer) {
    gat_body(blockIdx.x, gat_w, gat_as, gat_ad, layer);
}

// ---------------- mega layer-0 launch: gat l0 + wredL + wredP + inits ------
__global__ void __launch_bounds__(128) k_l0(
        const float* __restrict__ gat_w, const float* __restrict__ gat_as,
        const float* __restrict__ gat_ad, const float* __restrict__ W1,
        const float* __restrict__ se2_b) {
    int bx = blockIdx.x;
    int tid = threadIdx.x;
    if (bx < NB_GAT) {
        gat_body(bx, gat_w, gat_as, gat_ad, 0);
        return;
    }
    bx -= NB_GAT;
    if (bx < NB_WREDL) {
        // WL[i,n] = sum_j W[(i*192+j), n]
        int n = (bx & 15) * 128 + tid;
        if (n >= SEHID) return;
        int i = bx >> 4;
        const float* p = W1 + (size_t)(i * 192) * SEHID + n;
        float a0 = 0.f, a1 = 0.f, a2 = 0.f, a3 = 0.f;
#pragma unroll 2
        for (int j = 0; j < 192; j += 8) {
            a0 += p[(size_t)(j+0) * SEHID] + p[(size_t)(j+4) * SEHID];
            a1 += p[(size_t)(j+1) * SEHID] + p[(size_t)(j+5) * SEHID];
            a2 += p[(size_t)(j+2) * SEHID] + p[(size_t)(j+6) * SEHID];
            a3 += p[(size_t)(j+3) * SEHID] + p[(size_t)(j+7) * SEHID];
        }
        g_sew[i * SEHID + n] = (a0 + a1) + (a2 + a3);
        return;
    }
    bx -= NB_WREDL;
    if (bx < NB_WREDP) {
        // WP[j,n] = sum_i W[(i*192+j), n]
        int n = (bx & 15) * 128 + tid;
        if (n >= SEHID) return;
        int j = bx >> 4;
        const float* p = W1 + (size_t)j * SEHID + n;
        const size_t S = (size_t)192 * SEHID;
        float a0 = 0.f, a1 = 0.f, a2 = 0.f, a3 = 0.f;
        int i = 0;
#pragma unroll 2
        for (; i + 8 <= LL1; i += 8) {
            a0 += p[(i+0) * S] + p[(i+4) * S];
            a1 += p[(i+1) * S] + p[(i+5) * S];
            a2 += p[(i+2) * S] + p[(i+6) * S];
            a3 += p[(i+3) * S] + p[(i+7) * S];
        }
        for (; i < LL1; i++) a0 += p[i * S];
        g_sew[(LL1 + j) * SEHID + n] = (a0 + a1) + (a2 + a3);
        return;
    }
    bx -= NB_WREDP;
    if (bx < NB_ZC1) {
        int idx = bx * 128 + tid;
        if (idx < BSZ * SEHID) g_c1[idx] = 0.f;
        if (idx < BSZ * 256)   g_xx[idx] = 0.f;
        return;
    }
    bx -= NB_ZC1;
    {
        int idx = bx * 128 + tid;
        if (idx < BSZ * SEIN) g_c2[idx] = se2_b[idx % SEIN];
    }
}

// per-edge: accumulate unnormalized numerator + denominator in ONE pass
__global__ void k_edge(const int* __restrict__ dei, const int* __restrict__ pei) {
    int gid = blockIdx.x * blockDim.x + threadIdx.x;
    int e = gid >> 5, lane = gid & 31;
    if (e >= ETOT) return;
    int s, d;
    if (e < E1T) { s = dei[e]; d = dei[E1T + e]; }
    else { int q = e - E1T; s = pei[q] + ND; d = pei[E2T + q] + ND; }
    float w = 0.f;
    if (lane == 0) {
        w = expf(lrelu(g_hs[s] + g_hd[d]));
        atomicAdd(&g_den[d], w);
    }
    w = __shfl_sync(0xffffffffu, w, 0);
#pragma unroll
    for (int c = 0; c < 4; c++) {
        int f = lane + 32 * c;
        atomicAdd(&g_o[d * 128 + f], w * g_h[s * 128 + f]);
    }
}

// normalize + bias + relu + residual accum; last layer also does row sums
__global__ void k_final(const float* __restrict__ gat_b, int layer) {
    int gid = blockIdx.x * blockDim.x + threadIdx.x;
    int n = gid >> 5, lane = gid & 31;
    if (n >= NODES) return;
    int widx = (n < ND ? 0 : 3) + layer;
    float inv = 1.0f / g_den[n];
    float4 o = ((const float4*)&g_o[n * 128])[lane];
    float4 b = ((const float4*)&gat_b[widx * 128])[lane];
    float4 v;
    v.x = fmaxf(fmaf(o.x, inv, b.x), 0.f);
    v.y = fmaxf(fmaf(o.y, inv, b.y), 0.f);
    v.z = fmaxf(fmaf(o.z, inv, b.z), 0.f);
    v.w = fmaxf(fmaf(o.w, inv, b.w), 0.f);
    float4* xs4 = (float4*)&g_xsum[n * 128];
    float4 sum;
    if (layer == 0) sum = v;
    else {
        float4 p = xs4[lane];
        sum.x = p.x + v.x; sum.y = p.y + v.y; sum.z = p.z + v.z; sum.w = p.w + v.w;
    }
    xs4[lane] = sum;
    if (layer < 2) ((float4*)&g_x[n * 128])[lane] = v;
    else {
        float s = sum.x + sum.y + sum.z + sum.w;
#pragma unroll
        for (int o2 = 16; o2 > 0; o2 >>= 1) s += __shfl_down_sync(0xffffffffu, s, o2);
        if (lane == 0) g_rs[n] = s * (1.f / 256.f);
    }
}

// c1(32,2000) += [rl|rp](32, chunk of 271) @ g_sew + b ; split-K=4
__global__ void k_se1(const float* __restrict__ bias) {
    __shared__ float AsT[68][36];
    int tid = threadIdx.x;
    int n = blockIdx.x * 128 + tid;
    int k0 = blockIdx.y * 68;
    int k1 = min(SEK, k0 + 68);
    int klen = k1 - k0;
    for (int idx = tid; idx < 32 * klen; idx += 128) {
        int m = idx / klen, kk = idx - m * klen;
        int k = k0 + kk;
        float v = (k < LL1) ? g_rs[m * LL1 + k] : g_rs[ND + m * LL2 + (k - LL1)];
        AsT[kk][m] = v;
    }
    __syncthreads();
    if (n >= SEHID) return;
    unsigned long long acc[16];
    if (blockIdx.y == 0) {
        float bn = bias[n];
        unsigned long long bp = pack2(bn, bn);
#pragma unroll
        for (int q = 0; q < 16; q++) acc[q] = bp;
    } else {
#pragma unroll
        for (int q = 0; q < 16; q++) acc[q] = 0ULL;
    }
    unsigned sbase = (unsigned)__cvta_generic_to_shared(&AsT[0][0]);
#pragma unroll 4
    for (int kk = 0; kk < klen; kk++) {
        float w = g_sew[(k0 + kk) * SEHID + n];
        unsigned long long w2 = pack2(w, w);
        unsigned row = sbase + (unsigned)kk * 144;
#pragma unroll
        for (int q = 0; q < 8; q++) {
            unsigned long long a0, a1;
            lds_v2u64(row + q * 16, a0, a1);
            fma2(acc[2 * q], a0, w2);
            fma2(acc[2 * q + 1], a1, w2);
        }
    }
#pragma unroll
    for (int q = 0; q < 16; q++) {
        float lo, hi; unpack2(acc[q], lo, hi);
        atomicAdd(&g_c1[(2 * q) * SEHID + n], lo);
        atomicAdd(&g_c1[(2 * q + 1) * SEHID + n], hi);
    }
}

// c2 += relu(c1) @ se2_w ; f32x2, split-K=8 (chunks of 250)
#define TK2 50
__global__ void k_se2(const float* __restrict__ W) {
    __shared__ float AsT[TK2][36];
    int tid = threadIdx.x;
    int n = blockIdx.x * 128 + tid;
    int k0 = blockIdx.y * 250;
    bool valid = (n < SEIN);
    unsigned long long acc[16];
#pragma unroll
    for (int q = 0; q < 16; q++) acc[q] = 0ULL;
    unsigned sbase = (unsigned)__cvta_generic_to_shared(&AsT[0][0]);
    for (int kk = k0; kk < k0 + 250; kk += TK2) {
        __syncthreads();
        for (int idx = tid; idx < 32 * TK2; idx += 128) {
            int m = idx / TK2, t = idx - m * TK2;
            AsT[t][m] = fmaxf(g_c1[m * SEHID + kk + t], 0.f);
        }
        __syncthreads();
        if (valid) {
            const float* wp = W + (size_t)kk * SEIN + n;
#pragma unroll 5
            for (int t = 0; t < TK2; t++) {
                float w = wp[(size_t)t * SEIN];
                unsigned long long w2 = pack2(w, w);
                unsigned row = sbase + (unsigned)t * 144;
#pragma unroll
                for (int q = 0; q < 8; q++) {
                    unsigned long long a0, a1;
                    lds_v2u64(row + q * 16, a0, a1);
                    fma2(acc[2 * q], a0, w2);
                    fma2(acc[2 * q + 1], a1, w2);
                }
            }
        }
    }
    if (valid) {
#pragma unroll
        for (int q = 0; q < 16; q++) {
            float lo, hi; unpack2(acc[q], lo, hi);
            atomicAdd(&g_c2[(size_t)(2 * q) * SEIN + n], lo);
            atomicAdd(&g_c2[(size_t)(2 * q + 1) * SEIN + n], hi);
        }
    }
}

// sigmoid folded; wl[b,i] and wp[b,j] weighted sums
__global__ void k_wlp(const float* __restrict__ inter) {
    int gid = blockIdx.x * blockDim.x + threadIdx.x;
    int w = gid >> 5, lane = gid & 31;
    if (w < BSZ * LL1) {
        int b = w / LL1, i = w - b * LL1;
        float s = 0.f;
        for (int j = lane; j < LL2; j += 32) {
            int idx = b * SEIN + i * LL2 + j;
            float sg = 1.f / (1.f + expf(-g_c2[idx]));
            s += sg / inter[idx];
        }
#pragma unroll
        for (int o = 16; o > 0; o >>= 1) s += __shfl_down_sync(0xffffffffu, s, o);
        if (lane == 0) g_wl[w] = s * (1.f / (float)SEIN);
    } else if (w < BSZ * (LL1 + LL2)) {
        int w2i = w - BSZ * LL1;
        int b = w2i / LL2, j = w2i - b * LL2;
        float s = 0.f;
        for (int i = lane; i < LL1; i += 32) {
            int idx = b * SEIN + i * LL2 + j;
            float sg = 1.f / (1.f + expf(-g_c2[idx]));
            s += sg / inter[idx];
        }
#pragma unroll
        for (int o = 16; o > 0; o >>= 1) s += __shfl_down_sync(0xffffffffu, s, o);
        if (lane == 0) g_wp[w2i] = s * (1.f / (float)SEIN);
    }
}

// xx split over 8 reduction segments + atomicAdd (g_xx zero-inited in k_l0)
__global__ void k_fuse() {
    int b = blockIdx.x, seg = blockIdx.y, t = threadIdx.x;   // 128 threads
    float acc = 0.f;
    if (seg < 4) {
        int i0 = seg * 20, i1 = min(LL1, i0 + 20);
        for (int i = i0; i < i1; i++)
            acc = fmaf(g_wl[b * LL1 + i], g_xsum[(b * LL1 + i) * HIDD + t], acc);
        atomicAdd(&g_xx[b * 256 + t], acc);
    } else {
        int j0 = (seg - 4) * 48;
        for (int j = j0; j < j0 + 48; j++)
            acc = fmaf(g_wp[b * LL2 + j], g_xsum[(ND + b * LL2 + j) * HIDD + t], acc);
        atomicAdd(&g_xx[b * 256 + 128 + t], acc);
    }
}

// ---------------- fused head MLP: one block per batch row, K-split fc2/fc3/fc4
__global__ void __launch_bounds__(512) k_head(
    const float* __restrict__ fc1_w, const float* __restrict__ fc1_b,
    const float* __restrict__ fc2_w, const float* __restrict__ fc2_b,
    const float* __restrict__ fc3_w, const float* __restrict__ fc3_b,
    const float* __restrict__ fc4_w, const float* __restrict__ fc4_b,
    const float* __restrict__ out_w, const float* __restrict__ out_b,
    float* __restrict__ dout) {
    int b = blockIdx.x, t = threadIdx.x;
    __shared__ float s0[256], s1[512], s2[256], s3[128], s4[64];
    __shared__ float p2[512];
    if (t < 256) s0[t] = g_xx[b * 256 + t];
    __syncthreads();
    // fc1: 256 -> 512 (h1 pre-relu is an output)
    {
        float acc = fc1_b[t];
#pragma unroll 8
        for (int k = 0; k < 256; k++) acc = fmaf(s0[k], fc1_w[k * 512 + t], acc);
        dout[32 + b * 512 + t] = acc;
        s1[t] = fmaxf(acc, 0.f);
    }
    __syncthreads();
    // fc2: 512 -> 256, K split 2-way
    {
        int n = t & 255, half = t >> 8;
        int kb = half * 256;
        float acc = 0.f;
#pragma unroll 8
        for (int k = 0; k < 256; k++) acc = fmaf(s1[kb + k], fc2_w[(kb + k) * 256 + n], acc);
        p2[t] = acc;
    }
    __syncthreads();
    if (t < 256) s2[t] = fmaxf(p2[t] + p2[t + 256] + fc2_b[t], 0.f);
    __syncthreads();
    // fc3: 256 -> 128, K split 4-way
    {
        int n = t & 127, q = t >> 7;
        int kb = q * 64;
        float acc = 0.f;
#pragma unroll 8
        for (int k = 0; k < 64; k++) acc = fmaf(s2[kb + k], fc3_w[(kb + k) * 128 + n], acc);
        p2[t] = acc;
    }
    __syncthreads();
    if (t < 128)
        s3[t] = fmaxf(p2[t] + p2[t + 128] + p2[t + 256] + p2[t + 384] + fc3_b[t], 0.f);
    __syncthreads();
    // fc4: 128 -> 64, K split 8-way
    {
        int n = t & 63, q = t >> 6;
        int kb = q * 16;
        float acc = 0.f;
#pragma unroll
        for (int k = 0; k < 16; k++) acc = fmaf(s3[kb + k], fc4_w[(kb + k) * 64 + n], acc);
        p2[t] = acc;
    }
    __syncthreads();
    if (t < 64) {
        float acc = fc4_b[t];
#pragma unroll
        for (int q = 0; q < 8; q++) acc += p2[t + 64 * q];
        s4[t] = fmaxf(acc, 0.f);
    }
    __syncthreads();
    // out: 64 -> 1
    if (t < 32) {
        float acc = s4[t] * out_w[t] + s4[t + 32] * out_w[t + 32];
#pragma unroll
        for (int o = 16; o > 0; o >>= 1) acc += __shfl_down_sync(0xffffffffu, acc, o);
        if (t == 0) dout[b] = acc + out_b[0];
    }
}

extern "C" void kernel_launch(void* const* d_in, const int* in_sizes, int n_in,
                              void* d_out, int out_size) {
    const float* x1    = (const float*)d_in[0];
    const float* x2    = (const float*)d_in[1];
    const float* inter = (const float*)d_in[2];
    const int*   dei   = (const int*)d_in[3];
    const int*   pei   = (const int*)d_in[4];
    const float* w1    = (const float*)d_in[5];
    const float* b1    = (const float*)d_in[6];
    const float* w2    = (const float*)d_in[7];
    const float* b2    = (const float*)d_in[8];
    const float* gat_w = (const float*)d_in[9];
    const float* gat_as= (const float*)d_in[10];
    const float* gat_ad= (const float*)d_in[11];
    const float* gat_b = (const float*)d_in[12];
    const float* se1_w = (const float*)d_in[13];
    const float* se1_b = (const float*)d_in[14];
    const float* se2_w = (const float*)d_in[15];
    const float* se2_b = (const float*)d_in[16];
    const float* fc1_w = (const float*)d_in[17];
    const float* fc1_b = (const float*)d_in[18];
    const float* fc2_w = (const float*)d_in[19];
    const float* fc2_b = (const float*)d_in[20];
    const float* fc3_w = (const float*)d_in[21];
    const float* fc3_b = (const float*)d_in[22];
    const float* fc4_w = (const float*)d_in[23];
    const float* fc4_b = (const float*)d_in[24];
    const float* out_w = (const float*)d_in[25];
    const float* out_b = (const float*)d_in[26];
    float* dout = (float*)d_out;

    k_embed<<<NODES / 8, 128>>>(x1, x2, w1, b1, w2, b2);

    // layer 0: GAT GEMM + (overlapped) se1_w reductions + c1/c2/xx inits
    k_l0<<<NB_TOTAL, 128>>>(gat_w, gat_as, gat_ad, se1_w, se2_b);
    k_edge<<<(ETOT * 32 + 255) / 256, 256>>>(dei, pei);
    k_final<<<(NODES * 32 + 255) / 256, 256>>>(gat_b, 0);

    for (int l = 1; l < 3; l++) {
        k_gat_h<<<NODES / 8, 128>>>(gat_w, gat_as, gat_ad, l);
        k_edge<<<(ETOT * 32 + 255) / 256, 256>>>(dei, pei);
        k_final<<<(NODES * 32 + 255) / 256, 256>>>(gat_b, l);
    }

    k_se1<<<dim3(16, 4), 128>>>(se1_b);
    k_se2<<<dim3(119, 8), 128>>>(se2_w);

    k_wlp<<<(BSZ * (LL1 + LL2) * 32 + 255) / 256, 256>>>(inter);
    k_fuse<<<dim3(BSZ, 8), 128>>>();

    k_head<<<BSZ, 512>>>(fc1_w, fc1_b, fc2_w, fc2_b, fc3_w, fc3_b,
                         fc4_w, fc4_b, out_w, out_b, dout);
}

// round 16
// speedup vs baseline: 2.1934x; 1.0627x over previous
#include <cuda_runtime.h>
#include <math.h>

#define NODES 8672
#define ND    2528
#define HIDD  128
#define BSZ   32
#define LL1   79
#define LL2   192
#define E1T   5120
#define E2T   12800
#define ETOT  17920
#define SEIN  15168
#define SEHID 2000
#define SEK   271      // 79 + 192

// mega-launch block ranges
#define NB_GAT   1084
#define NB_EMB   1084
#define NB_WREDL 1264          // 16 ncol x 79 i   (runs with embed)
#define NB_WREDP 3072          // 16 ncol x 192 j  (runs with gat l0)
#define NB_ZC1   500           // 64000 / 128
#define NB_BC2   3792          // 485376 / 128
#define NB_EMBTOT (NB_EMB + NB_WREDL)
#define NB_L0TOT  (NB_GAT + NB_WREDP + NB_ZC1 + NB_BC2)

// ---------------- device scratch ----------------
__device__ float g_x   [NODES*HIDD];
__device__ float g_h   [NODES*HIDD];
__device__ float g_o   [NODES*HIDD];     // unnormalized numerator
__device__ float g_xsum[NODES*HIDD];
__device__ float g_hs[NODES], g_hd[NODES], g_den[NODES];
__device__ float g_rs[NODES];            // row sums / 256
__device__ float g_sew[SEK*SEHID];       // [0:79) WL rows, [79:271) WP rows
__device__ float g_c1[BSZ*SEHID];
__device__ float g_c2[BSZ*SEIN];
__device__ float g_wl[BSZ*LL1], g_wp[BSZ*LL2];
__device__ float g_xx[BSZ*256];

__device__ __forceinline__ float lrelu(float x) { return x > 0.f ? x : 0.2f * x; }

// ---- f32x2 helpers ----
__device__ __forceinline__ void fma2(unsigned long long& d, unsigned long long a, unsigned long long b) {
    asm("fma.rn.f32x2 %0, %1, %2, %0;" : "+l"(d) : "l"(a), "l"(b));
}
__device__ __forceinline__ unsigned long long pack2(float x, float y) {
    unsigned long long r;
    asm("mov.b64 %0, {%1, %2};" : "=l"(r) : "f"(x), "f"(y));
    return r;
}
__device__ __forceinline__ void unpack2(unsigned long long v, float& x, float& y) {
    asm("mov.b64 {%0, %1}, %2;" : "=f"(x), "=f"(y) : "l"(v));
}
__device__ __forceinline__ void lds_v2u64(unsigned saddr, unsigned long long& a, unsigned long long& b) {
    asm volatile("ld.shared.v2.u64 {%0,%1}, [%2];" : "=l"(a), "=l"(b) : "r"(saddr));
}

// ---------------- embedding MLP body (8 rows / block) ----------------
__device__ __forceinline__ void embed_body(int bx,
                        const float* __restrict__ x1, const float* __restrict__ x2,
                        const float* __restrict__ w1, const float* __restrict__ b1,
                        const float* __restrict__ w2, const float* __restrict__ b2) {
    __shared__ float xsT[52][8];
    __shared__ float hbT[128][8];
    int tid = threadIdx.x;
    int r0 = bx * 8;
    for (int idx = tid; idx < 8 * 52; idx += 128) {
        int r = idx / 52, c = idx - r * 52;
        int row = r0 + r;
        xsT[c][r] = (row < ND) ? x1[row * 52 + c] : x2[(row - ND) * 52 + c];
    }
    __syncthreads();
    float acc[8] = {0.f,0.f,0.f,0.f,0.f,0.f,0.f,0.f};
    for (int k = 0; k < 52; k++) {
        float w = w1[k * 128 + tid];
        float4 a0 = *(const float4*)&xsT[k][0];
        float4 a1 = *(const float4*)&xsT[k][4];
        acc[0] = fmaf(a0.x, w, acc[0]); acc[1] = fmaf(a0.y, w, acc[1]);
        acc[2] = fmaf(a0.z, w, acc[2]); acc[3] = fmaf(a0.w, w, acc[3]);
        acc[4] = fmaf(a1.x, w, acc[4]); acc[5] = fmaf(a1.y, w, acc[5]);
        acc[6] = fmaf(a1.z, w, acc[6]); acc[7] = fmaf(a1.w, w, acc[7]);
    }
    float bv = b1[tid];
#pragma unroll
    for (int r = 0; r < 8; r++) hbT[tid][r] = fmaxf(acc[r] + bv, 0.f);
    __syncthreads();
    float a2[8] = {0.f,0.f,0.f,0.f,0.f,0.f,0.f,0.f};
    for (int k = 0; k < 128; k++) {
        float w = w2[k * 128 + tid];
        float4 a0 = *(const float4*)&hbT[k][0];
        float4 a1 = *(const float4*)&hbT[k][4];
        a2[0] = fmaf(a0.x, w, a2[0]); a2[1] = fmaf(a0.y, w, a2[1]);
        a2[2] = fmaf(a0.z, w, a2[2]); a2[3] = fmaf(a0.w, w, a2[3]);
        a2[4] = fmaf(a1.x, w, a2[4]); a2[5] = fmaf(a1.y, w, a2[5]);
        a2[6] = fmaf(a1.z, w, a2[6]); a2[7] = fmaf(a1.w, w, a2[7]);
    }
    float b2v = b2[tid];
#pragma unroll
    for (int r = 0; r < 8; r++)
        g_x[(r0 + r) * 128 + tid] = fmaxf(a2[r] + b2v, 0.f);
}

// embed + (overlapped) wredL
__global__ void __launch_bounds__(128) k_emb(
        const float* __restrict__ x1, const float* __restrict__ x2,
        const float* __restrict__ w1, const float* __restrict__ b1,
        const float* __restrict__ w2, const float* __restrict__ b2,
        const float* __restrict__ W1) {
    int bx = blockIdx.x;
    int tid = threadIdx.x;
    if (bx < NB_EMB) { embed_body(bx, x1, x2, w1, b1, w2, b2); return; }
    bx -= NB_EMB;
    // WL[i,n] = sum_j W[(i*192+j), n]
    int n = (bx & 15) * 128 + tid;
    if (n >= SEHID) return;
    int i = bx >> 4;
    const float* p = W1 + (size_t)(i * 192) * SEHID + n;
    float a0 = 0.f, a1 = 0.f, a2 = 0.f, a3 = 0.f;
#pragma unroll 2
    for (int j = 0; j < 192; j += 8) {
        a0 += p[(size_t)(j+0) * SEHID] + p[(size_t)(j+4) * SEHID];
        a1 += p[(size_t)(j+1) * SEHID] + p[(size_t)(j+5) * SEHID];
        a2 += p[(size_t)(j+2) * SEHID] + p[(size_t)(j+6) * SEHID];
        a3 += p[(size_t)(j+3) * SEHID] + p[(size_t)(j+7) * SEHID];
    }
    g_sew[i * SEHID + n] = (a0 + a1) + (a2 + a3);
}

// ---------------- GAT GEMM core (shared tile already filled) -------------
__device__ __forceinline__ void gat_core(int r0, const float xsT[128][8],
                                         const float* __restrict__ gat_w,
                                         const float* __restrict__ gat_as,
                                         const float* __restrict__ gat_ad, int layer) {
    __shared__ float redS[8][4], redD[8][4];
    __shared__ float sws[8];
    int tid = threadIdx.x;
    int widx = (r0 < ND ? 0 : 3) + layer;
    const float* W = gat_w + (size_t)widx * 16384;
    float acc[8] = {0.f,0.f,0.f,0.f,0.f,0.f,0.f,0.f};
#pragma unroll 8
    for (int k = 0; k < 128; k++) {
        float w = W[k * 128 + tid];
        float4 a0 = *(const float4*)&xsT[k][0];
        float4 a1 = *(const float4*)&xsT[k][4];
        acc[0] = fmaf(a0.x, w, acc[0]); acc[1] = fmaf(a0.y, w, acc[1]);
        acc[2] = fmaf(a0.z, w, acc[2]); acc[3] = fmaf(a0.w, w, acc[3]);
        acc[4] = fmaf(a1.x, w, acc[4]); acc[5] = fmaf(a1.y, w, acc[5]);
        acc[6] = fmaf(a1.z, w, acc[6]); acc[7] = fmaf(a1.w, w, acc[7]);
    }
    float asv = gat_as[widx * 128 + tid], adv = gat_ad[widx * 128 + tid];
    int lane = tid & 31, wrp = tid >> 5;
#pragma unroll
    for (int r = 0; r < 8; r++) {
        float ps = acc[r] * asv, pd = acc[r] * adv;
#pragma unroll
        for (int o = 16; o > 0; o >>= 1) {
            ps += __shfl_down_sync(0xffffffffu, ps, o);
            pd += __shfl_down_sync(0xffffffffu, pd, o);
        }
        if (lane == 0) { redS[r][wrp] = ps; redD[r][wrp] = pd; }
    }
    __syncthreads();
    if (tid < 8) {
        float hs = redS[tid][0] + redS[tid][1] + redS[tid][2] + redS[tid][3];
        float hd = redD[tid][0] + redD[tid][1] + redD[tid][2] + redD[tid][3];
        g_hs[r0 + tid] = hs; g_hd[r0 + tid] = hd;
        float w = expf(lrelu(hs + hd));   // self-loop weight (shift-free softmax)
        g_den[r0 + tid] = w;
        sws[tid] = w;
    }
    __syncthreads();
#pragma unroll
    for (int r = 0; r < 8; r++) {
        g_h[(r0 + r) * 128 + tid] = acc[r];
        g_o[(r0 + r) * 128 + tid] = sws[r] * acc[r];
    }
}

// layer-0 gat body: reads g_x
__device__ __forceinline__ void gat_body0(int bx, const float* __restrict__ gat_w,
                                          const float* __restrict__ gat_as,
                                          const float* __restrict__ gat_ad) {
    __shared__ float xsT[128][8];
    int tid = threadIdx.x;
    int r0 = bx * 8;
    for (int idx = tid; idx < 1024; idx += 128) {
        int r = idx >> 7, k = idx & 127;
        xsT[k][r] = g_x[(r0 + r) * 128 + k];
    }
    __syncthreads();
    gat_core(r0, xsT, gat_w, gat_as, gat_ad, 0);
}

// layers 1,2: fuse previous layer's finalize (normalize+bias+relu+xsum) into load
__global__ void __launch_bounds__(128) k_gat_fused(
        const float* __restrict__ gat_w, const float* __restrict__ gat_as,
        const float* __restrict__ gat_ad, const float* __restrict__ gat_b,
        int layer) {
    __shared__ float xsT[128][8];
    __shared__ float sinv[8];
    int tid = threadIdx.x;
    int r0 = blockIdx.x * 8;
    int widxp = (r0 < ND ? 0 : 3) + layer - 1;
    if (tid < 8) sinv[tid] = 1.0f / g_den[r0 + tid];
    __syncthreads();
    const float* bp = gat_b + widxp * 128;
    for (int idx = tid; idx < 1024; idx += 128) {
        int r = idx >> 7, k = idx & 127;
        int n = r0 + r;
        float v = fmaxf(fmaf(g_o[n * 128 + k], sinv[r], bp[k]), 0.f);
        xsT[k][r] = v;
        g_xsum[n * 128 + k] = (layer == 1) ? v : (g_xsum[n * 128 + k] + v);
    }
    __syncthreads();
    gat_core(r0, xsT, gat_w, gat_as, gat_ad, layer);
}

// ---------------- mega layer-0 launch: gat l0 + wredP + inits ------
__global__ void __launch_bounds__(128) k_l0(
        const float* __restrict__ gat_w, const float* __restrict__ gat_as,
        const float* __restrict__ gat_ad, const float* __restrict__ W1,
        const float* __restrict__ se2_b) {
    int bx = blockIdx.x;
    int tid = threadIdx.x;
    if (bx < NB_GAT) {
        gat_body0(bx, gat_w, gat_as, gat_ad);
        return;
    }
    bx -= NB_GAT;
    if (bx < NB_WREDP) {
        // WP[j,n] = sum_i W[(i*192+j), n]
        int n = (bx & 15) * 128 + tid;
        if (n >= SEHID) return;
        int j = bx >> 4;
        const float* p = W1 + (size_t)j * SEHID + n;
        const size_t S = (size_t)192 * SEHID;
        float a0 = 0.f, a1 = 0.f, a2 = 0.f, a3 = 0.f;
        int i = 0;
#pragma unroll 2
        for (; i + 8 <= LL1; i += 8) {
            a0 += p[(i+0) * S] + p[(i+4) * S];
            a1 += p[(i+1) * S] + p[(i+5) * S];
            a2 += p[(i+2) * S] + p[(i+6) * S];
            a3 += p[(i+3) * S] + p[(i+7) * S];
        }
        for (; i < LL1; i++) a0 += p[i * S];
        g_sew[(LL1 + j) * SEHID + n] = (a0 + a1) + (a2 + a3);
        return;
    }
    bx -= NB_WREDP;
    if (bx < NB_ZC1) {
        int idx = bx * 128 + tid;
        if (idx < BSZ * SEHID) g_c1[idx] = 0.f;
        if (idx < BSZ * 256)   g_xx[idx] = 0.f;
        return;
    }
    bx -= NB_ZC1;
    {
        int idx = bx * 128 + tid;
        if (idx < BSZ * SEIN) g_c2[idx] = se2_b[idx % SEIN];
    }
}

// per-edge: accumulate unnormalized numerator + denominator in ONE pass
__global__ void k_edge(const int* __restrict__ dei, const int* __restrict__ pei) {
    int gid = blockIdx.x * blockDim.x + threadIdx.x;
    int e = gid >> 5, lane = gid & 31;
    if (e >= ETOT) return;
    int s, d;
    if (e < E1T) { s = dei[e]; d = dei[E1T + e]; }
    else { int q = e - E1T; s = pei[q] + ND; d = pei[E2T + q] + ND; }
    float w = 0.f;
    if (lane == 0) {
        w = expf(lrelu(g_hs[s] + g_hd[d]));
        atomicAdd(&g_den[d], w);
    }
    w = __shfl_sync(0xffffffffu, w, 0);
#pragma unroll
    for (int c = 0; c < 4; c++) {
        int f = lane + 32 * c;
        atomicAdd(&g_o[d * 128 + f], w * g_h[s * 128 + f]);
    }
}

// layer-2 finalize: normalize + bias + relu + xsum accum + row sums
__global__ void k_final(const float* __restrict__ gat_b) {
    int gid = blockIdx.x * blockDim.x + threadIdx.x;
    int n = gid >> 5, lane = gid & 31;
    if (n >= NODES) return;
    int widx = (n < ND ? 0 : 3) + 2;
    float inv = 1.0f / g_den[n];
    float4 o = ((const float4*)&g_o[n * 128])[lane];
    float4 b = ((const float4*)&gat_b[widx * 128])[lane];
    float4 v;
    v.x = fmaxf(fmaf(o.x, inv, b.x), 0.f);
    v.y = fmaxf(fmaf(o.y, inv, b.y), 0.f);
    v.z = fmaxf(fmaf(o.z, inv, b.z), 0.f);
    v.w = fmaxf(fmaf(o.w, inv, b.w), 0.f);
    float4* xs4 = (float4*)&g_xsum[n * 128];
    float4 p = xs4[lane];
    float4 sum;
    sum.x = p.x + v.x; sum.y = p.y + v.y; sum.z = p.z + v.z; sum.w = p.w + v.w;
    xs4[lane] = sum;
    float s = sum.x + sum.y + sum.z + sum.w;
#pragma unroll
    for (int o2 = 16; o2 > 0; o2 >>= 1) s += __shfl_down_sync(0xffffffffu, s, o2);
    if (lane == 0) g_rs[n] = s * (1.f / 256.f);
}

// c1(32,2000) += [rl|rp](32, chunk of 271) @ g_sew + b ; split-K=4
__global__ void k_se1(const float* __restrict__ bias) {
    __shared__ float AsT[68][36];
    int tid = threadIdx.x;
    int n = blockIdx.x * 128 + tid;
    int k0 = blockIdx.y * 68;
    int k1 = min(SEK, k0 + 68);
    int klen = k1 - k0;
    for (int idx = tid; idx < 32 * klen; idx += 128) {
        int m = idx / klen, kk = idx - m * klen;
        int k = k0 + kk;
        float v = (k < LL1) ? g_rs[m * LL1 + k] : g_rs[ND + m * LL2 + (k - LL1)];
        AsT[kk][m] = v;
    }
    __syncthreads();
    if (n >= SEHID) return;
    unsigned long long acc[16];
    if (blockIdx.y == 0) {
        float bn = bias[n];
        unsigned long long bp = pack2(bn, bn);
#pragma unroll
        for (int q = 0; q < 16; q++) acc[q] = bp;
    } else {
#pragma unroll
        for (int q = 0; q < 16; q++) acc[q] = 0ULL;
    }
    unsigned sbase = (unsigned)__cvta_generic_to_shared(&AsT[0][0]);
#pragma unroll 4
    for (int kk = 0; kk < klen; kk++) {
        float w = g_sew[(k0 + kk) * SEHID + n];
        unsigned long long w2 = pack2(w, w);
        unsigned row = sbase + (unsigned)kk * 144;
#pragma unroll
        for (int q = 0; q < 8; q++) {
            unsigned long long a0, a1;
            lds_v2u64(row + q * 16, a0, a1);
            fma2(acc[2 * q], a0, w2);
            fma2(acc[2 * q + 1], a1, w2);
        }
    }
#pragma unroll
    for (int q = 0; q < 16; q++) {
        float lo, hi; unpack2(acc[q], lo, hi);
        atomicAdd(&g_c1[(2 * q) * SEHID + n], lo);
        atomicAdd(&g_c1[(2 * q + 1) * SEHID + n], hi);
    }
}

// c2 += relu(c1) @ se2_w ; f32x2, split-K=8 (chunks of 250)
#define TK2 50
__global__ void k_se2(const float* __restrict__ W) {
    __shared__ float AsT[TK2][36];
    int tid = threadIdx.x;
    int n = blockIdx.x * 128 + tid;
    int k0 = blockIdx.y * 250;
    bool valid = (n < SEIN);
    unsigned long long acc[16];
#pragma unroll
    for (int q = 0; q < 16; q++) acc[q] = 0ULL;
    unsigned sbase = (unsigned)__cvta_generic_to_shared(&AsT[0][0]);
    for (int kk = k0; kk < k0 + 250; kk += TK2) {
        __syncthreads();
        for (int idx = tid; idx < 32 * TK2; idx += 128) {
            int m = idx / TK2, t = idx - m * TK2;
            AsT[t][m] = fmaxf(g_c1[m * SEHID + kk + t], 0.f);
        }
        __syncthreads();
        if (valid) {
            const float* wp = W + (size_t)kk * SEIN + n;
#pragma unroll 5
            for (int t = 0; t < TK2; t++) {
                float w = wp[(size_t)t * SEIN];
                unsigned long long w2 = pack2(w, w);
                unsigned row = sbase + (unsigned)t * 144;
#pragma unroll
                for (int q = 0; q < 8; q++) {
                    unsigned long long a0, a1;
                    lds_v2u64(row + q * 16, a0, a1);
                    fma2(acc[2 * q], a0, w2);
                    fma2(acc[2 * q + 1], a1, w2);
                }
            }
        }
    }
    if (valid) {
#pragma unroll
        for (int q = 0; q < 16; q++) {
            float lo, hi; unpack2(acc[q], lo, hi);
            atomicAdd(&g_c2[(size_t)(2 * q) * SEIN + n], lo);
            atomicAdd(&g_c2[(size_t)(2 * q + 1) * SEIN + n], hi);
        }
    }
}

// sigmoid folded; wl[b,i] and wp[b,j] weighted sums
__global__ void k_wlp(const float* __restrict__ inter) {
    int gid = blockIdx.x * blockDim.x + threadIdx.x;
    int w = gid >> 5, lane = gid & 31;
    if (w < BSZ * LL1) {
        int b = w / LL1, i = w - b * LL1;
        float s = 0.f;
        for (int j = lane; j < LL2; j += 32) {
            int idx = b * SEIN + i * LL2 + j;
            float sg = 1.f / (1.f + expf(-g_c2[idx]));
            s += sg / inter[idx];
        }
#pragma unroll
        for (int o = 16; o > 0; o >>= 1) s += __shfl_down_sync(0xffffffffu, s, o);
        if (lane == 0) g_wl[w] = s * (1.f / (float)SEIN);
    } else if (w < BSZ * (LL1 + LL2)) {
        int w2i = w - BSZ * LL1;
        int b = w2i / LL2, j = w2i - b * LL2;
        float s = 0.f;
        for (int i = lane; i < LL1; i += 32) {
            int idx = b * SEIN + i * LL2 + j;
            float sg = 1.f / (1.f + expf(-g_c2[idx]));
            s += sg / inter[idx];
        }
#pragma unroll
        for (int o = 16; o > 0; o >>= 1) s += __shfl_down_sync(0xffffffffu, s, o);
        if (lane == 0) g_wp[w2i] = s * (1.f / (float)SEIN);
    }
}

// xx split over 8 reduction segments + atomicAdd (g_xx zero-inited in k_l0)
__global__ void k_fuse() {
    int b = blockIdx.x, seg = blockIdx.y, t = threadIdx.x;   // 128 threads
    float acc = 0.f;
    if (seg < 4) {
        int i0 = seg * 20, i1 = min(LL1, i0 + 20);
        for (int i = i0; i < i1; i++)
            acc = fmaf(g_wl[b * LL1 + i], g_xsum[(b * LL1 + i) * HIDD + t], acc);
        atomicAdd(&g_xx[b * 256 + t], acc);
    } else {
        int j0 = (seg - 4) * 48;
        for (int j = j0; j < j0 + 48; j++)
            acc = fmaf(g_wp[b * LL2 + j], g_xsum[(ND + b * LL2 + j) * HIDD + t], acc);
        atomicAdd(&g_xx[b * 256 + 128 + t], acc);
    }
}

// ---------------- fused head MLP: one block per batch row, K-split fc2/fc3/fc4
__global__ void __launch_bounds__(512) k_head(
    const float* __restrict__ fc1_w, const float* __restrict__ fc1_b,
    const float* __restrict__ fc2_w, const float* __restrict__ fc2_b,
    const float* __restrict__ fc3_w, const float* __restrict__ fc3_b,
    const float* __restrict__ fc4_w, const float* __restrict__ fc4_b,
    const float* __restrict__ out_w, const float* __restrict__ out_b,
    float* __restrict__ dout) {
    int b = blockIdx.x, t = threadIdx.x;
    __shared__ float s0[256], s1[512], s2[256], s3[128], s4[64];
    __shared__ float p2[512];
    if (t < 256) s0[t] = g_xx[b * 256 + t];
    __syncthreads();
    // fc1: 256 -> 512 (h1 pre-relu is an output)
    {
        float acc = fc1_b[t];
#pragma unroll 8
        for (int k = 0; k < 256; k++) acc = fmaf(s0[k], fc1_w[k * 512 + t], acc);
        dout[32 + b * 512 + t] = acc;
        s1[t] = fmaxf(acc, 0.f);
    }
    __syncthreads();
    // fc2: 512 -> 256, K split 2-way
    {
        int n = t & 255, half = t >> 8;
        int kb = half * 256;
        float acc = 0.f;
#pragma unroll 8
        for (int k = 0; k < 256; k++) acc = fmaf(s1[kb + k], fc2_w[(kb + k) * 256 + n], acc);
        p2[t] = acc;
    }
    __syncthreads();
    if (t < 256) s2[t] = fmaxf(p2[t] + p2[t + 256] + fc2_b[t], 0.f);
    __syncthreads();
    // fc3: 256 -> 128, K split 4-way
    {
        int n = t & 127, q = t >> 7;
        int kb = q * 64;
        float acc = 0.f;
#pragma unroll 8
        for (int k = 0; k < 64; k++) acc = fmaf(s2[kb + k], fc3_w[(kb + k) * 128 + n], acc);
        p2[t] = acc;
    }
    __syncthreads();
    if (t < 128)
        s3[t] = fmaxf(p2[t] + p2[t + 128] + p2[t + 256] + p2[t + 384] + fc3_b[t], 0.f);
    __syncthreads();
    // fc4: 128 -> 64, K split 8-way
    {
        int n = t & 63, q = t >> 6;
        int kb = q * 16;
        float acc = 0.f;
#pragma unroll
        for (int k = 0; k < 16; k++) acc = fmaf(s3[kb + k], fc4_w[(kb + k) * 64 + n], acc);
        p2[t] = acc;
    }
    __syncthreads();
    if (t < 64) {
        float acc = fc4_b[t];
#pragma unroll
        for (int q = 0; q < 8; q++) acc += p2[t + 64 * q];
        s4[t] = fmaxf(acc, 0.f);
    }
    __syncthreads();
    // out: 64 -> 1
    if (t < 32) {
        float acc = s4[t] * out_w[t] + s4[t + 32] * out_w[t + 32];
#pragma unroll
        for (int o = 16; o > 0; o >>= 1) acc += __shfl_down_sync(0xffffffffu, acc, o);
        if (t == 0) dout[b] = acc + out_b[0];
    }
}

extern "C" void kernel_launch(void* const* d_in, const int* in_sizes, int n_in,
                              void* d_out, int out_size) {
    const float* x1    = (const float*)d_in[0];
    const float* x2    = (const float*)d_in[1];
    const float* inter = (const float*)d_in[2];
    const int*   dei   = (const int*)d_in[3];
    const int*   pei   = (const int*)d_in[4];
    const float* w1    = (const float*)d_in[5];
    const float* b1    = (const float*)d_in[6];
    const float* w2    = (const float*)d_in[7];
    const float* b2    = (const float*)d_in[8];
    const float* gat_w = (const float*)d_in[9];
    const float* gat_as= (const float*)d_in[10];
    const float* gat_ad= (const float*)d_in[11];
    const float* gat_b = (const float*)d_in[12];
    const float* se1_w = (const float*)d_in[13];
    const float* se1_b = (const float*)d_in[14];
    const float* se2_w = (const float*)d_in[15];
    const float* se2_b = (const float*)d_in[16];
    const float* fc1_w = (const float*)d_in[17];
    const float* fc1_b = (const float*)d_in[18];
    const float* fc2_w = (const float*)d_in[19];
    const float* fc2_b = (const float*)d_in[20];
    const float* fc3_w = (const float*)d_in[21];
    const float* fc3_b = (const float*)d_in[22];
    const float* fc4_w = (const float*)d_in[23];
    const float* fc4_b = (const float*)d_in[24];
    const float* out_w = (const float*)d_in[25];
    const float* out_b = (const float*)d_in[26];
    float* dout = (float*)d_out;

    // embed + (overlapped) wredL
    k_emb<<<NB_EMBTOT, 128>>>(x1, x2, w1, b1, w2, b2, se1_w);

    // layer 0: GAT GEMM + (overlapped) wredP + c1/c2/xx inits
    k_l0<<<NB_L0TOT, 128>>>(gat_w, gat_as, gat_ad, se1_w, se2_b);
    k_edge<<<(ETOT * 32 + 255) / 256, 256>>>(dei, pei);

    // layers 1,2: previous finalize fused into the GEMM's load phase
    k_gat_fused<<<NODES / 8, 128>>>(gat_w, gat_as, gat_ad, gat_b, 1);
    k_edge<<<(ETOT * 32 + 255) / 256, 256>>>(dei, pei);
    k_gat_fused<<<NODES / 8, 128>>>(gat_w, gat_as, gat_ad, gat_b, 2);
    k_edge<<<(ETOT * 32 + 255) / 256, 256>>>(dei, pei);

    k_final<<<(NODES * 32 + 255) / 256, 256>>>(gat_b);

    k_se1<<<dim3(16, 4), 128>>>(se1_b);
    k_se2<<<dim3(119, 8), 128>>>(se2_w);

    k_wlp<<<(BSZ * (LL1 + LL2) * 32 + 255) / 256, 256>>>(inter);
    k_fuse<<<dim3(BSZ, 8), 128>>>();

    k_head<<<BSZ, 512>>>(fc1_w, fc1_b, fc2_w, fc2_b, fc3_w, fc3_b,
                         fc4_w, fc4_b, out_w, out_b, dout);
}

// round 17
// speedup vs baseline: 2.2066x; 1.0060x over previous
#include <cuda_runtime.h>
#include <math.h>

#define NODES 8672
#define ND    2528
#define HIDD  128
#define BSZ   32
#define LL1   79
#define LL2   192
#define E1T   5120
#define E2T   12800
#define ETOT  17920
#define SEIN  15168
#define SEHID 2000
#define SEK   271      // 79 + 192

// mega-launch block ranges
#define NB_GAT   1084
#define NB_EMB   1084
#define NB_WREDL 1264          // 16 ncol x 79 i   (runs with embed)
#define NB_WREDP 3072          // 16 ncol x 192 j  (runs with gat l0)
#define NB_ZC1   500           // 64000 / 128
#define NB_BC2   3792          // 485376 / 128
#define NB_EMBTOT (NB_EMB + NB_WREDL)
#define NB_L0TOT  (NB_GAT + NB_WREDP + NB_ZC1 + NB_BC2)

// ---------------- device scratch ----------------
__device__ float g_x   [NODES*HIDD];
__device__ float g_h   [NODES*HIDD];
__device__ float g_o   [NODES*HIDD];     // unnormalized numerator
__device__ float g_xsum[NODES*HIDD];
__device__ float g_hs[NODES], g_hd[NODES], g_den[NODES];
__device__ float g_rs[NODES];            // row sums / 256
__device__ float g_sew[SEK*SEHID];       // [0:79) WL rows, [79:271) WP rows
__device__ float g_c1[BSZ*SEHID];
__device__ float g_c2[BSZ*SEIN];
__device__ float g_wl[BSZ*LL1], g_wp[BSZ*LL2];
__device__ float g_xx[BSZ*256];

__device__ __forceinline__ float lrelu(float x) { return x > 0.f ? x : 0.2f * x; }

// ---- f32x2 helpers ----
__device__ __forceinline__ void fma2(unsigned long long& d, unsigned long long a, unsigned long long b) {
    asm("fma.rn.f32x2 %0, %1, %2, %0;" : "+l"(d) : "l"(a), "l"(b));
}
__device__ __forceinline__ unsigned long long pack2(float x, float y) {
    unsigned long long r;
    asm("mov.b64 %0, {%1, %2};" : "=l"(r) : "f"(x), "f"(y));
    return r;
}
__device__ __forceinline__ void unpack2(unsigned long long v, float& x, float& y) {
    asm("mov.b64 {%0, %1}, %2;" : "=f"(x), "=f"(y) : "l"(v));
}
__device__ __forceinline__ void lds_v2u64(unsigned saddr, unsigned long long& a, unsigned long long& b) {
    asm volatile("ld.shared.v2.u64 {%0,%1}, [%2];" : "=l"(a), "=l"(b) : "r"(saddr));
}

// ---------------- embedding MLP body (8 rows / block) ----------------
__device__ __forceinline__ void embed_body(int bx,
                        const float* __restrict__ x1, const float* __restrict__ x2,
                        const float* __restrict__ w1, const float* __restrict__ b1,
                        const float* __restrict__ w2, const float* __restrict__ b2) {
    __shared__ float xsT[52][8];
    __shared__ float hbT[128][8];
    int tid = threadIdx.x;
    int r0 = bx * 8;
    for (int idx = tid; idx < 8 * 52; idx += 128) {
        int r = idx / 52, c = idx - r * 52;
        int row = r0 + r;
        xsT[c][r] = (row < ND) ? x1[row * 52 + c] : x2[(row - ND) * 52 + c];
    }
    __syncthreads();
    float acc[8] = {0.f,0.f,0.f,0.f,0.f,0.f,0.f,0.f};
    for (int k = 0; k < 52; k++) {
        float w = w1[k * 128 + tid];
        float4 a0 = *(const float4*)&xsT[k][0];
        float4 a1 = *(const float4*)&xsT[k][4];
        acc[0] = fmaf(a0.x, w, acc[0]); acc[1] = fmaf(a0.y, w, acc[1]);
        acc[2] = fmaf(a0.z, w, acc[2]); acc[3] = fmaf(a0.w, w, acc[3]);
        acc[4] = fmaf(a1.x, w, acc[4]); acc[5] = fmaf(a1.y, w, acc[5]);
        acc[6] = fmaf(a1.z, w, acc[6]); acc[7] = fmaf(a1.w, w, acc[7]);
    }
    float bv = b1[tid];
#pragma unroll
    for (int r = 0; r < 8; r++) hbT[tid][r] = fmaxf(acc[r] + bv, 0.f);
    __syncthreads();
    float a2[8] = {0.f,0.f,0.f,0.f,0.f,0.f,0.f,0.f};
    for (int k = 0; k < 128; k++) {
        float w = w2[k * 128 + tid];
        float4 a0 = *(const float4*)&hbT[k][0];
        float4 a1 = *(const float4*)&hbT[k][4];
        a2[0] = fmaf(a0.x, w, a2[0]); a2[1] = fmaf(a0.y, w, a2[1]);
        a2[2] = fmaf(a0.z, w, a2[2]); a2[3] = fmaf(a0.w, w, a2[3]);
        a2[4] = fmaf(a1.x, w, a2[4]); a2[5] = fmaf(a1.y, w, a2[5]);
        a2[6] = fmaf(a1.z, w, a2[6]); a2[7] = fmaf(a1.w, w, a2[7]);
    }
    float b2v = b2[tid];
#pragma unroll
    for (int r = 0; r < 8; r++)
        g_x[(r0 + r) * 128 + tid] = fmaxf(a2[r] + b2v, 0.f);
}

// embed + (overlapped) wredL
__global__ void __launch_bounds__(128) k_emb(
        const float* __restrict__ x1, const float* __restrict__ x2,
        const float* __restrict__ w1, const float* __restrict__ b1,
        const float* __restrict__ w2, const float* __restrict__ b2,
        const float* __restrict__ W1) {
    int bx = blockIdx.x;
    int tid = threadIdx.x;
    if (bx < NB_EMB) { embed_body(bx, x1, x2, w1, b1, w2, b2); return; }
    bx -= NB_EMB;
    // WL[i,n] = sum_j W[(i*192+j), n]
    int n = (bx & 15) * 128 + tid;
    if (n >= SEHID) return;
    int i = bx >> 4;
    const float* p = W1 + (size_t)(i * 192) * SEHID + n;
    float a0 = 0.f, a1 = 0.f, a2 = 0.f, a3 = 0.f;
#pragma unroll 2
    for (int j = 0; j < 192; j += 8) {
        a0 += p[(size_t)(j+0) * SEHID] + p[(size_t)(j+4) * SEHID];
        a1 += p[(size_t)(j+1) * SEHID] + p[(size_t)(j+5) * SEHID];
        a2 += p[(size_t)(j+2) * SEHID] + p[(size_t)(j+6) * SEHID];
        a3 += p[(size_t)(j+3) * SEHID] + p[(size_t)(j+7) * SEHID];
    }
    g_sew[i * SEHID + n] = (a0 + a1) + (a2 + a3);
}

// ---------------- GAT GEMM core (shared tile already filled) -------------
// f32x2 packed FMA: rows paired in u64 accumulators; bit-identical to scalar.
__device__ __forceinline__ void gat_core(int r0, const float xsT[128][8],
                                         const float* __restrict__ gat_w,
                                         const float* __restrict__ gat_as,
                                         const float* __restrict__ gat_ad, int layer) {
    __shared__ float redS[8][4], redD[8][4];
    __shared__ float sws[8];
    int tid = threadIdx.x;
    int widx = (r0 < ND ? 0 : 3) + layer;
    const float* W = gat_w + (size_t)widx * 16384;
    unsigned long long acc2[4] = {0ULL, 0ULL, 0ULL, 0ULL};
    unsigned sbase = (unsigned)__cvta_generic_to_shared(&xsT[0][0]);
#pragma unroll 8
    for (int k = 0; k < 128; k++) {
        float w = W[k * 128 + tid];
        unsigned long long w2 = pack2(w, w);
        unsigned long long a0, a1, b0, b1;
        lds_v2u64(sbase + (unsigned)k * 32, a0, a1);
        lds_v2u64(sbase + (unsigned)k * 32 + 16, b0, b1);
        fma2(acc2[0], a0, w2);
        fma2(acc2[1], a1, w2);
        fma2(acc2[2], b0, w2);
        fma2(acc2[3], b1, w2);
    }
    float acc[8];
    unpack2(acc2[0], acc[0], acc[1]);
    unpack2(acc2[1], acc[2], acc[3]);
    unpack2(acc2[2], acc[4], acc[5]);
    unpack2(acc2[3], acc[6], acc[7]);
    float asv = gat_as[widx * 128 + tid], adv = gat_ad[widx * 128 + tid];
    int lane = tid & 31, wrp = tid >> 5;
#pragma unroll
    for (int r = 0; r < 8; r++) {
        float ps = acc[r] * asv, pd = acc[r] * adv;
#pragma unroll
        for (int o = 16; o > 0; o >>= 1) {
            ps += __shfl_down_sync(0xffffffffu, ps, o);
            pd += __shfl_down_sync(0xffffffffu, pd, o);
        }
        if (lane == 0) { redS[r][wrp] = ps; redD[r][wrp] = pd; }
    }
    __syncthreads();
    if (tid < 8) {
        float hs = redS[tid][0] + redS[tid][1] + redS[tid][2] + redS[tid][3];
        float hd = redD[tid][0] + redD[tid][1] + redD[tid][2] + redD[tid][3];
        g_hs[r0 + tid] = hs; g_hd[r0 + tid] = hd;
        float w = expf(lrelu(hs + hd));   // self-loop weight (shift-free softmax)
        g_den[r0 + tid] = w;
        sws[tid] = w;
    }
    __syncthreads();
#pragma unroll
    for (int r = 0; r < 8; r++) {
        g_h[(r0 + r) * 128 + tid] = acc[r];
        g_o[(r0 + r) * 128 + tid] = sws[r] * acc[r];
    }
}

// layer-0 gat body: reads g_x
__device__ __forceinline__ void gat_body0(int bx, const float* __restrict__ gat_w,
                                          const float* __restrict__ gat_as,
                                          const float* __restrict__ gat_ad) {
    __shared__ float xsT[128][8];
    int tid = threadIdx.x;
    int r0 = bx * 8;
    for (int idx = tid; idx < 1024; idx += 128) {
        int r = idx >> 7, k = idx & 127;
        xsT[k][r] = g_x[(r0 + r) * 128 + k];
    }
    __syncthreads();
    gat_core(r0, xsT, gat_w, gat_as, gat_ad, 0);
}

// layers 1,2: fuse previous layer's finalize (normalize+bias+relu+xsum) into load
__global__ void __launch_bounds__(128) k_gat_fused(
        const float* __restrict__ gat_w, const float* __restrict__ gat_as,
        const float* __restrict__ gat_ad, const float* __restrict__ gat_b,
        int layer) {
    __shared__ float xsT[128][8];
    __shared__ float sinv[8];
    int tid = threadIdx.x;
    int r0 = blockIdx.x * 8;
    int widxp = (r0 < ND ? 0 : 3) + layer - 1;
    if (tid < 8) sinv[tid] = 1.0f / g_den[r0 + tid];
    __syncthreads();
    const float* bp = gat_b + widxp * 128;
    for (int idx = tid; idx < 1024; idx += 128) {
        int r = idx >> 7, k = idx & 127;
        int n = r0 + r;
        float v = fmaxf(fmaf(g_o[n * 128 + k], sinv[r], bp[k]), 0.f);
        xsT[k][r] = v;
        g_xsum[n * 128 + k] = (layer == 1) ? v : (g_xsum[n * 128 + k] + v);
    }
    __syncthreads();
    gat_core(r0, xsT, gat_w, gat_as, gat_ad, layer);
}

// ---------------- mega layer-0 launch: gat l0 + wredP + inits ------
__global__ void __launch_bounds__(128) k_l0(
        const float* __restrict__ gat_w, const float* __restrict__ gat_as,
        const float* __restrict__ gat_ad, const float* __restrict__ W1,
        const float* __restrict__ se2_b) {
    int bx = blockIdx.x;
    int tid = threadIdx.x;
    if (bx < NB_GAT) {
        gat_body0(bx, gat_w, gat_as, gat_ad);
        return;
    }
    bx -= NB_GAT;
    if (bx < NB_WREDP) {
        // WP[j,n] = sum_i W[(i*192+j), n]
        int n = (bx & 15) * 128 + tid;
        if (n >= SEHID) return;
        int j = bx >> 4;
        const float* p = W1 + (size_t)j * SEHID + n;
        const size_t S = (size_t)192 * SEHID;
        float a0 = 0.f, a1 = 0.f, a2 = 0.f, a3 = 0.f;
        int i = 0;
#pragma unroll 2
        for (; i + 8 <= LL1; i += 8) {
            a0 += p[(i+0) * S] + p[(i+4) * S];
            a1 += p[(i+1) * S] + p[(i+5) * S];
            a2 += p[(i+2) * S] + p[(i+6) * S];
            a3 += p[(i+3) * S] + p[(i+7) * S];
        }
        for (; i < LL1; i++) a0 += p[i * S];
        g_sew[(LL1 + j) * SEHID + n] = (a0 + a1) + (a2 + a3);
        return;
    }
    bx -= NB_WREDP;
    if (bx < NB_ZC1) {
        int idx = bx * 128 + tid;
        if (idx < BSZ * SEHID) g_c1[idx] = 0.f;
        if (idx < BSZ * 256)   g_xx[idx] = 0.f;
        return;
    }
    bx -= NB_ZC1;
    {
        int idx = bx * 128 + tid;
        if (idx < BSZ * SEIN) g_c2[idx] = se2_b[idx % SEIN];
    }
}

// per-edge: accumulate unnormalized numerator + denominator in ONE pass
__global__ void k_edge(const int* __restrict__ dei, const int* __restrict__ pei) {
    int gid = blockIdx.x * blockDim.x + threadIdx.x;
    int e = gid >> 5, lane = gid & 31;
    if (e >= ETOT) return;
    int s, d;
    if (e < E1T) { s = dei[e]; d = dei[E1T + e]; }
    else { int q = e - E1T; s = pei[q] + ND; d = pei[E2T + q] + ND; }
    float w = 0.f;
    if (lane == 0) {
        w = expf(lrelu(g_hs[s] + g_hd[d]));
        atomicAdd(&g_den[d], w);
    }
    w = __shfl_sync(0xffffffffu, w, 0);
#pragma unroll
    for (int c = 0; c < 4; c++) {
        int f = lane + 32 * c;
        atomicAdd(&g_o[d * 128 + f], w * g_h[s * 128 + f]);
    }
}

// layer-2 finalize: normalize + bias + relu + xsum accum + row sums
__global__ void k_final(const float* __restrict__ gat_b) {
    int gid = blockIdx.x * blockDim.x + threadIdx.x;
    int n = gid >> 5, lane = gid & 31;
    if (n >= NODES) return;
    int widx = (n < ND ? 0 : 3) + 2;
    float inv = 1.0f / g_den[n];
    float4 o = ((const float4*)&g_o[n * 128])[lane];
    float4 b = ((const float4*)&gat_b[widx * 128])[lane];
    float4 v;
    v.x = fmaxf(fmaf(o.x, inv, b.x), 0.f);
    v.y = fmaxf(fmaf(o.y, inv, b.y), 0.f);
    v.z = fmaxf(fmaf(o.z, inv, b.z), 0.f);
    v.w = fmaxf(fmaf(o.w, inv, b.w), 0.f);
    float4* xs4 = (float4*)&g_xsum[n * 128];
    float4 p = xs4[lane];
    float4 sum;
    sum.x = p.x + v.x; sum.y = p.y + v.y; sum.z = p.z + v.z; sum.w = p.w + v.w;
    xs4[lane] = sum;
    float s = sum.x + sum.y + sum.z + sum.w;
#pragma unroll
    for (int o2 = 16; o2 > 0; o2 >>= 1) s += __shfl_down_sync(0xffffffffu, s, o2);
    if (lane == 0) g_rs[n] = s * (1.f / 256.f);
}

// c1(32,2000) += [rl|rp](32, chunk of 271) @ g_sew + b ; split-K=4
__global__ void k_se1(const float* __restrict__ bias) {
    __shared__ float AsT[68][36];
    int tid = threadIdx.x;
    int n = blockIdx.x * 128 + tid;
    int k0 = blockIdx.y * 68;
    int k1 = min(SEK, k0 + 68);
    int klen = k1 - k0;
    for (int idx = tid; idx < 32 * klen; idx += 128) {
        int m = idx / klen, kk = idx - m * klen;
        int k = k0 + kk;
        float v = (k < LL1) ? g_rs[m * LL1 + k] : g_rs[ND + m * LL2 + (k - LL1)];
        AsT[kk][m] = v;
    }
    __syncthreads();
    if (n >= SEHID) return;
    unsigned long long acc[16];
    if (blockIdx.y == 0) {
        float bn = bias[n];
        unsigned long long bp = pack2(bn, bn);
#pragma unroll
        for (int q = 0; q < 16; q++) acc[q] = bp;
    } else {
#pragma unroll
        for (int q = 0; q < 16; q++) acc[q] = 0ULL;
    }
    unsigned sbase = (unsigned)__cvta_generic_to_shared(&AsT[0][0]);
#pragma unroll 4
    for (int kk = 0; kk < klen; kk++) {
        float w = g_sew[(k0 + kk) * SEHID + n];
        unsigned long long w2 = pack2(w, w);
        unsigned row = sbase + (unsigned)kk * 144;
#pragma unroll
        for (int q = 0; q < 8; q++) {
            unsigned long long a0, a1;
            lds_v2u64(row + q * 16, a0, a1);
            fma2(acc[2 * q], a0, w2);
            fma2(acc[2 * q + 1], a1, w2);
        }
    }
#pragma unroll
    for (int q = 0; q < 16; q++) {
        float lo, hi; unpack2(acc[q], lo, hi);
        atomicAdd(&g_c1[(2 * q) * SEHID + n], lo);
        atomicAdd(&g_c1[(2 * q + 1) * SEHID + n], hi);
    }
}

// c2 += relu(c1) @ se2_w ; f32x2, split-K=8 (chunks of 250)
#define TK2 50
__global__ void k_se2(const float* __restrict__ W) {
    __shared__ float AsT[TK2][36];
    int tid = threadIdx.x;
    int n = blockIdx.x * 128 + tid;
    int k0 = blockIdx.y * 250;
    bool valid = (n < SEIN);
    unsigned long long acc[16];
#pragma unroll
    for (int q = 0; q < 16; q++) acc[q] = 0ULL;
    unsigned sbase = (unsigned)__cvta_generic_to_shared(&AsT[0][0]);
    for (int kk = k0; kk < k0 + 250; kk += TK2) {
        __syncthreads();
        for (int idx = tid; idx < 32 * TK2; idx += 128) {
            int m = idx / TK2, t = idx - m * TK2;
            AsT[t][m] = fmaxf(g_c1[m * SEHID + kk + t], 0.f);
        }
        __syncthreads();
        if (valid) {
            const float* wp = W + (size_t)kk * SEIN + n;
#pragma unroll 5
            for (int t = 0; t < TK2; t++) {
                float w = wp[(size_t)t * SEIN];
                unsigned long long w2 = pack2(w, w);
                unsigned row = sbase + (unsigned)t * 144;
#pragma unroll
                for (int q = 0; q < 8; q++) {
                    unsigned long long a0, a1;
                    lds_v2u64(row + q * 16, a0, a1);
                    fma2(acc[2 * q], a0, w2);
                    fma2(acc[2 * q + 1], a1, w2);
                }
            }
        }
    }
    if (valid) {
#pragma unroll
        for (int q = 0; q < 16; q++) {
            float lo, hi; unpack2(acc[q], lo, hi);
            atomicAdd(&g_c2[(size_t)(2 * q) * SEIN + n], lo);
            atomicAdd(&g_c2[(size_t)(2 * q + 1) * SEIN + n], hi);
        }
    }
}

// sigmoid folded; wl[b,i] and wp[b,j] weighted sums
__global__ void k_wlp(const float* __restrict__ inter) {
    int gid = blockIdx.x * blockDim.x + threadIdx.x;
    int w = gid >> 5, lane = gid & 31;
    if (w < BSZ * LL1) {
        int b = w / LL1, i = w - b * LL1;
        float s = 0.f;
        for (int j = lane; j < LL2; j += 32) {
            int idx = b * SEIN + i * LL2 + j;
            float sg = 1.f / (1.f + expf(-g_c2[idx]));
            s += sg / inter[idx];
        }
#pragma unroll
        for (int o = 16; o > 0; o >>= 1) s += __shfl_down_sync(0xffffffffu, s, o);
        if (lane == 0) g_wl[w] = s * (1.f / (float)SEIN);
    } else if (w < BSZ * (LL1 + LL2)) {
        int w2i = w - BSZ * LL1;
        int b = w2i / LL2, j = w2i - b * LL2;
        float s = 0.f;
        for (int i = lane; i < LL1; i += 32) {
            int idx = b * SEIN + i * LL2 + j;
            float sg = 1.f / (1.f + expf(-g_c2[idx]));
            s += sg / inter[idx];
        }
#pragma unroll
        for (int o = 16; o > 0; o >>= 1) s += __shfl_down_sync(0xffffffffu, s, o);
        if (lane == 0) g_wp[w2i] = s * (1.f / (float)SEIN);
    }
}

// xx split over 8 reduction segments + atomicAdd (g_xx zero-inited in k_l0)
__global__ void k_fuse() {
    int b = blockIdx.x, seg = blockIdx.y, t = threadIdx.x;   // 128 threads
    float acc = 0.f;
    if (seg < 4) {
        int i0 = seg * 20, i1 = min(LL1, i0 + 20);
        for (int i = i0; i < i1; i++)
            acc = fmaf(g_wl[b * LL1 + i], g_xsum[(b * LL1 + i) * HIDD + t], acc);
        atomicAdd(&g_xx[b * 256 + t], acc);
    } else {
        int j0 = (seg - 4) * 48;
        for (int j = j0; j < j0 + 48; j++)
            acc = fmaf(g_wp[b * LL2 + j], g_xsum[(ND + b * LL2 + j) * HIDD + t], acc);
        atomicAdd(&g_xx[b * 256 + 128 + t], acc);
    }
}

// ---------------- fused head MLP: one block per batch row, K-split fc2/fc3/fc4
__global__ void __launch_bounds__(512) k_head(
    const float* __restrict__ fc1_w, const float* __restrict__ fc1_b,
    const float* __restrict__ fc2_w, const float* __restrict__ fc2_b,
    const float* __restrict__ fc3_w, const float* __restrict__ fc3_b,
    const float* __restrict__ fc4_w, const float* __restrict__ fc4_b,
    const float* __restrict__ out_w, const float* __restrict__ out_b,
    float* __restrict__ dout) {
    int b = blockIdx.x, t = threadIdx.x;
    __shared__ float s0[256], s1[512], s2[256], s3[128], s4[64];
    __shared__ float p2[512];
    if (t < 256) s0[t] = g_xx[b * 256 + t];
    __syncthreads();
    // fc1: 256 -> 512 (h1 pre-relu is an output)
    {
        float acc = fc1_b[t];
#pragma unroll 8
        for (int k = 0; k < 256; k++) acc = fmaf(s0[k], fc1_w[k * 512 + t], acc);
        dout[32 + b * 512 + t] = acc;
        s1[t] = fmaxf(acc, 0.f);
    }
    __syncthreads();
    // fc2: 512 -> 256, K split 2-way
    {
        int n = t & 255, half = t >> 8;
        int kb = half * 256;
        float acc = 0.f;
#pragma unroll 8
        for (int k = 0; k < 256; k++) acc = fmaf(s1[kb + k], fc2_w[(kb + k) * 256 + n], acc);
        p2[t] = acc;
    }
    __syncthreads();
    if (t < 256) s2[t] = fmaxf(p2[t] + p2[t + 256] + fc2_b[t], 0.f);
    __syncthreads();
    // fc3: 256 -> 128, K split 4-way
    {
        int n = t & 127, q = t >> 7;
        int kb = q * 64;
        float acc = 0.f;
#pragma unroll 8
        for (int k = 0; k < 64; k++) acc = fmaf(s2[kb + k], fc3_w[(kb + k) * 128 + n], acc);
        p2[t] = acc;
    }
    __syncthreads();
    if (t < 128)
        s3[t] = fmaxf(p2[t] + p2[t + 128] + p2[t + 256] + p2[t + 384] + fc3_b[t], 0.f);
    __syncthreads();
    // fc4: 128 -> 64, K split 8-way
    {
        int n = t & 63, q = t >> 6;
        int kb = q * 16;
        float acc = 0.f;
#pragma unroll
        for (int k = 0; k < 16; k++) acc = fmaf(s3[kb + k], fc4_w[(kb + k) * 64 + n], acc);
        p2[t] = acc;
    }
    __syncthreads();
    if (t < 64) {
        float acc = fc4_b[t];
#pragma unroll
        for (int q = 0; q < 8; q++) acc += p2[t + 64 * q];
        s4[t] = fmaxf(acc, 0.f);
    }
    __syncthreads();
    // out: 64 -> 1
    if (t < 32) {
        float acc = s4[t] * out_w[t] + s4[t + 32] * out_w[t + 32];
#pragma unroll
        for (int o = 16; o > 0; o >>= 1) acc += __shfl_down_sync(0xffffffffu, acc, o);
        if (t == 0) dout[b] = acc + out_b[0];
    }
}

extern "C" void kernel_launch(void* const* d_in, const int* in_sizes, int n_in,
                              void* d_out, int out_size) {
    const float* x1    = (const float*)d_in[0];
    const float* x2    = (const float*)d_in[1];
    const float* inter = (const float*)d_in[2];
    const int*   dei   = (const int*)d_in[3];
    const int*   pei   = (const int*)d_in[4];
    const float* w1    = (const float*)d_in[5];
    const float* b1    = (const float*)d_in[6];
    const float* w2    = (const float*)d_in[7];
    const float* b2    = (const float*)d_in[8];
    const float* gat_w = (const float*)d_in[9];
    const float* gat_as= (const float*)d_in[10];
    const float* gat_ad= (const float*)d_in[11];
    const float* gat_b = (const float*)d_in[12];
    const float* se1_w = (const float*)d_in[13];
    const float* se1_b = (const float*)d_in[14];
    const float* se2_w = (const float*)d_in[15];
    const float* se2_b = (const float*)d_in[16];
    const float* fc1_w = (const float*)d_in[17];
    const float* fc1_b = (const float*)d_in[18];
    const float* fc2_w = (const float*)d_in[19];
    const float* fc2_b = (const float*)d_in[20];
    const float* fc3_w = (const float*)d_in[21];
    const float* fc3_b = (const float*)d_in[22];
    const float* fc4_w = (const float*)d_in[23];
    const float* fc4_b = (const float*)d_in[24];
    const float* out_w = (const float*)d_in[25];
    const float* out_b = (const float*)d_in[26];
    float* dout = (float*)d_out;

    // embed + (overlapped) wredL
    k_emb<<<NB_EMBTOT, 128>>>(x1, x2, w1, b1, w2, b2, se1_w);

    // layer 0: GAT GEMM + (overlapped) wredP + c1/c2/xx inits
    k_l0<<<NB_L0TOT, 128>>>(gat_w, gat_as, gat_ad, se1_w, se2_b);
    k_edge<<<(ETOT * 32 + 255) / 256, 256>>>(dei, pei);

    // layers 1,2: previous finalize fused into the GEMM's load phase
    k_gat_fused<<<NODES / 8, 128>>>(gat_w, gat_as, gat_ad, gat_b, 1);
    k_edge<<<(ETOT * 32 + 255) / 256, 256>>>(dei, pei);
    k_gat_fused<<<NODES / 8, 128>>>(gat_w, gat_as, gat_ad, gat_b, 2);
    k_edge<<<(ETOT * 32 + 255) / 256, 256>>>(dei, pei);

    k_final<<<(NODES * 32 + 255) / 256, 256>>>(gat_b);

    k_se1<<<dim3(16, 4), 128>>>(se1_b);
    k_se2<<<dim3(119, 8), 128>>>(se2_w);

    k_wlp<<<(BSZ * (LL1 + LL2) * 32 + 255) / 256, 256>>>(inter);
    k_fuse<<<dim3(BSZ, 8), 128>>>();

    k_head<<<BSZ, 512>>>(fc1_w, fc1_b, fc2_w, fc2_b, fc3_w, fc3_b,
                         fc4_w, fc4_b, out_w, out_b, dout);
}